// round 12
// baseline (speedup 1.0000x reference)
#include <cuda_runtime.h>
#include <math.h>

typedef unsigned long long ull;

// Problem constants
#define BB   256
#define TT   512
#define IND  128
#define NI   149
#define NCC  99
#define NM   8
#define CAT0 277
#define CAT1 248
#define CAT2 107
#define K0P  288          // 9 chunks x 32
#define K1P  260          // 5 chunks x 52
#define RW   8            // batch rows per cluster
#define CL   4
#define NTH  480
#define WS0  128          // fused W0 row stride (3*40=120 active)
#define WS1  96           // fused W1 row stride (3*28=84 active)

// SMEM layout (float offsets)
#define XB0F  (K0P * 8)   // 2304
#define XB1F  (K1P * 8)   // 2080
#define XB2F  (112 * 8)   // 896
#define OFF_XH0   0
#define OFF_XH1   4608
#define OFF_XH2   8768
#define OFF_PARTA 10560   // 9*3*40*8 = 8640
#define OFF_PARTB 19200   // 5*3*28*8 = 3360
#define OFF_SW2   22560   // 3*107*8 = 2568
#define OFF_MBAR  25128   // 8 mbarriers = 16 floats
#define SMEM_FLOATS 25144
#define SMEM_BYTES  (SMEM_FLOATS * 4)   // ~100.6 KB

#define MB_RDYA(s)  (OFF_MBAR + 0 + 2*(s))
#define MB_CONB(s)  (OFF_MBAR + 4 + 2*(s))
#define MB_RDYB(s)  (OFF_MBAR + 8 + 2*(s))
#define MB_CONC(s)  (OFF_MBAR + 12 + 2*(s))

// Fused per-rank weight arrays (k-row packs mat0|mat1|mat2 j-quarter contiguously)
__device__ float g_W0q[4][K0P * WS0];
__device__ float g_W1q[4][K1P * WS1];
__device__ float g_W2[3][CAT2 * 8];
__device__ float g_bc[NI + NCC + NM];

// ---------------------------------------------------------------------------
__global__ void cfc_precompute_kernel(
    const float* __restrict__ w1_0, const float* __restrict__ w2_0,
    const float* __restrict__ wa_0, const float* __restrict__ wb_0,
    const float* __restrict__ ba_0, const float* __restrict__ bb_0,
    const int*   __restrict__ m0,
    const float* __restrict__ w1_1, const float* __restrict__ w2_1,
    const float* __restrict__ wa_1, const float* __restrict__ wb_1,
    const float* __restrict__ ba_1, const float* __restrict__ bb_1,
    const int*   __restrict__ m1,
    const float* __restrict__ w1_2, const float* __restrict__ w2_2,
    const float* __restrict__ wa_2, const float* __restrict__ wb_2,
    const float* __restrict__ ba_2, const float* __restrict__ bb_2,
    const int*   __restrict__ m2,
    const float* __restrict__ dt)
{
    const float ts = dt[0];
    const int idx    = blockIdx.x * blockDim.x + threadIdx.x;
    const int stride = gridDim.x * blockDim.x;

    // layer-0: rank r: j-quarter base r*38, nj {38,38,38,35}; col c = mat*40 + jl
    for (int i = idx; i < 4 * K0P * WS0; i += stride) {
        int r = i / (K0P * WS0), rem = i - r * (K0P * WS0);
        int k = rem / WS0, c = rem - k * WS0;
        float v = 0.f;
        if (c < 120 && k < CAT0) {
            int mat = c / 40, jl = c - mat * 40;
            int nj = (r < 3) ? 38 : 35;
            if (jl < nj) {
                int j = r * 38 + jl;
                int src = j * CAT0 + k;
                float mm = (float)m0[src];
                if (mat == 0)      v = w1_0[src] * mm;
                else if (mat == 1) v = w2_0[src] * mm;
                else               v = ts * wa_0[src] + wb_0[src];
            }
        }
        g_W0q[r][k * WS0 + c] = v;
    }
    // layer-1: j-quarter base r*25, nj {25,25,25,24}; col c = mat*28 + jl
    for (int i = idx; i < 4 * K1P * WS1; i += stride) {
        int r = i / (K1P * WS1), rem = i - r * (K1P * WS1);
        int k = rem / WS1, c = rem - k * WS1;
        float v = 0.f;
        if (c < 84 && k < CAT1) {
            int mat = c / 28, jl = c - mat * 28;
            int nj = (r < 3) ? 25 : 24;
            if (jl < nj) {
                int j = r * 25 + jl;
                int src = j * CAT1 + k;
                float mm = (float)m1[src];
                if (mat == 0)      v = w1_1[src] * mm;
                else if (mat == 1) v = w2_1[src] * mm;
                else               v = ts * wa_1[src] + wb_1[src];
            }
        }
        g_W1q[r][k * WS1 + c] = v;
    }
    for (int i = idx; i < CAT2 * 8; i += stride) {
        int k = i / 8, j = i - k * 8;
        int src = j * CAT2 + k;
        float mm = (float)m2[src];
        g_W2[0][i] = w1_2[src] * mm;
        g_W2[1][i] = w2_2[src] * mm;
        g_W2[2][i] = ts * wa_2[src] + wb_2[src];
    }
    for (int j = idx; j < NI;  j += stride) g_bc[j]            = ts * ba_0[j] + bb_0[j];
    for (int j = idx; j < NCC; j += stride) g_bc[NI + j]       = ts * ba_1[j] + bb_1[j];
    for (int j = idx; j < NM;  j += stride) g_bc[NI + NCC + j] = ts * ba_2[j] + bb_2[j];
}

// ---------------------------------------------------------------------------
__device__ __forceinline__ ull pack2(float a, float b) {
    ull r; asm("mov.b64 %0, {%1, %2};" : "=l"(r) : "f"(a), "f"(b)); return r;
}
__device__ __forceinline__ void unpack2(ull v, float& a, float& b) {
    asm("mov.b64 {%0, %1}, %2;" : "=f"(a), "=f"(b) : "l"(v));
}
__device__ __forceinline__ ull fma2(ull a, ull b, ull c) {
    ull d; asm("fma.rn.f32x2 %0, %1, %2, %3;" : "=l"(d) : "l"(a), "l"(b), "l"(c)); return d;
}
__device__ __forceinline__ ull add2(ull a, ull b) {
    ull d; asm("add.rn.f32x2 %0, %1, %2;" : "=l"(d) : "l"(a), "l"(b)); return d;
}
__device__ __forceinline__ float sigmoidf_(float z) { return 1.0f / (1.0f + expf(-z)); }
__device__ __forceinline__ float cfc_mix(float a1, float a2, float ac,
                                         float b1, float b2, float bc) {
    float ff1 = tanhf(a1 + b1);
    float ff2 = tanhf(a2 + b2);
    float ti  = sigmoidf_(ac + bc);
    return ff1 + ti * (ff2 - ff1);
}
__device__ __forceinline__ unsigned smem_u32(const void* p) {
    unsigned a;
    asm("{ .reg .u64 t; cvta.to.shared.u64 t, %1; cvt.u32.u64 %0, t; }" : "=r"(a) : "l"(p));
    return a;
}
__device__ __forceinline__ void mbar_init(unsigned addr, unsigned count) {
    asm volatile("mbarrier.init.shared.b64 [%0], %1;" :: "r"(addr), "r"(count) : "memory");
}
__device__ __forceinline__ void mbar_wait(unsigned addr, unsigned parity) {
    unsigned done = 0;
    do {
        asm volatile(
            "{\n\t.reg .pred P;\n\t"
            "mbarrier.try_wait.parity.acquire.cluster.shared::cta.b64 P, [%1], %2, 0x989680;\n\t"
            "selp.b32 %0, 1, 0, P;\n\t}"
            : "=r"(done) : "r"(addr), "r"(parity) : "memory");
    } while (!done);
}
__device__ __forceinline__ void mbar_arrive_local(unsigned addr) {
    asm volatile("mbarrier.arrive.release.cluster.shared::cta.b64 _, [%0];"
                 :: "r"(addr) : "memory");
}
__device__ __forceinline__ void mbar_arrive_rank(unsigned addr, unsigned r) {
    asm volatile(
        "{\n\t.reg .b32 ra;\n\t"
        "mapa.shared::cluster.u32 ra, %0, %1;\n\t"
        "mbarrier.arrive.release.cluster.shared::cluster.b64 _, [ra];\n\t}"
        :: "r"(addr), "r"(r) : "memory");
}
__device__ __forceinline__ void cfence() {
    asm volatile("fence.acq_rel.cluster;" ::: "memory");
}
__device__ __forceinline__ void st_rank_u64(unsigned addr, unsigned r, ull v) {
    asm volatile(
        "{\n\t.reg .b32 ra;\n\t"
        "mapa.shared::cluster.u32 ra, %0, %1;\n\t"
        "st.shared::cluster.u64 [ra], %2;\n\t}"
        :: "r"(addr), "r"(r), "l"(v) : "memory");
}
#define BARN(id, n) asm volatile("bar.sync %0, %1;" :: "r"(id), "r"(n) : "memory")

// Arrive on this mbar in ALL 4 cluster CTAs (local + 3 peers)
__device__ __forceinline__ void arrive_all(unsigned addr, unsigned rk) {
    #pragma unroll
    for (unsigned r = 0; r < 4; ++r) {
        if (r == rk) mbar_arrive_local(addr);
        else         mbar_arrive_rank(addr, r);
    }
}

// ---------------------------------------------------------------------------
// 32 clusters x 4 CTAs; cluster owns 8 batch rows; j split 4 ways.
// Warps 0-8 = layer0 (A), 9-13 = layer1 (B), warp 14 = layer2 (C), pipelined.
// Activations plain [k][8rows]; f32x2 lanes = row pairs.
// ---------------------------------------------------------------------------
__global__ __launch_bounds__(NTH, 1) __cluster_dims__(CL, 1, 1)
void cfc_main_kernel(
    const float* __restrict__ x,
    const float* __restrict__ b1_0, const float* __restrict__ b2_0,
    const float* __restrict__ b1_1, const float* __restrict__ b2_1,
    const float* __restrict__ b1_2, const float* __restrict__ b2_2,
    float* __restrict__ out, int write_h)
{
    extern __shared__ float sm[];
    float* xh0A  = sm + OFF_XH0;
    float* xh1A  = sm + OFF_XH1;
    float* xh2A  = sm + OFF_XH2;
    float* partA = sm + OFF_PARTA;
    float* partB = sm + OFF_PARTB;
    float* sw2   = sm + OFF_SW2;

    const int tid = threadIdx.x;
    unsigned rk;
    asm("mov.u32 %0, %%cluster_ctarank;" : "=r"(rk));
    const int b0 = (int)(blockIdx.x >> 2) * RW;

    const int nj0 = (rk < 3) ? 38 : 35;
    const int jb0 = (int)rk * 38;
    const int nj1 = (rk < 3) ? 25 : 24;
    const int jb1 = (int)rk * 25;

    const unsigned sbase = smem_u32(sm);

    const bool isA = (tid < 288);
    const bool isB = (tid >= 288 && tid < 448);

    // A: kc = tid>>5 (9 chunks of 32 k), combo = tid&31 (30 active: mat*10+jg)
    const int kcA = tid >> 5, comboA = tid & 31;
    const bool actA = isA && (comboA < 30);
    const int matA = comboA / 10, jgA = comboA - matA * 10;
    // A combine: tid<160: cj = tid%40, rp = tid/40
    const int cjA = tid % 40, rpA = tid / 40;
    const bool combA = (tid < 160) && (cjA < nj0);

    // B: bt: kc = bt>>5 (5 chunks of 52 k), combo = bt&31 (21 active: mat*7+jg)
    const int bt = tid - 288;
    const int kcB = bt >> 5, comboB = bt & 31;
    const bool actB = isB && (comboB < 21);
    const int matB = comboB / 7, jgB = comboB - matB * 7;
    const int cjB = bt % 28, rpB = bt / 28;
    const bool combB = isB && (bt < 112) && (cjB < nj1);

    // C
    const int ct = tid - 448;
    const int matC = ct >> 3, jC = ct & 7;
    const bool actC = (tid >= 448) && (ct < 24);

    // ---- prologue ----
    for (int i = tid; i < 2 * XB0F; i += NTH) xh0A[i] = 0.f;
    for (int i = tid; i < 2 * XB1F; i += NTH) xh1A[i] = 0.f;
    for (int i = tid; i < 2 * XB2F; i += NTH) xh2A[i] = 0.f;
    for (int i = tid; i < 3 * CAT2 * 8; i += NTH) sw2[i] = ((const float*)g_W2)[i];
    if (tid == 0) {
        for (int s = 0; s < 2; ++s) {
            mbar_init(sbase + MB_RDYA(s) * 4, 4);
            mbar_init(sbase + MB_CONB(s) * 4, 4);
            mbar_init(sbase + MB_RDYB(s) * 4, 4);
            mbar_init(sbase + MB_CONC(s) * 4, 4);
        }
    }

    float bA1 = 0.f, bA2 = 0.f, bAc = 0.f;
    if (combA) { bA1 = b1_0[jb0 + cjA]; bA2 = b2_0[jb0 + cjA]; bAc = g_bc[jb0 + cjA]; }
    float bB1 = 0.f, bB2 = 0.f, bBc = 0.f;
    if (combB) { bB1 = b1_1[jb1 + cjB]; bB2 = b2_1[jb1 + cjB]; bBc = g_bc[NI + jb1 + cjB]; }
    float bC1 = 0.f, bC2 = 0.f, bCc = 0.f;
    if (tid >= 448) { bC1 = b1_2[jC]; bC2 = b2_2[jC]; bCc = g_bc[NI + NCC + jC]; }

    // stage x_0 plain [k][8r] into buf0; A prefetches x_1 (4 regs)
    for (int i = tid; i < RW * IND; i += NTH) {
        int r = i >> 7, k = i & 127;
        xh0A[k * 8 + r] = x[((size_t)(b0 + r) * TT + 0) * IND + k];
    }
    float xr[4] = {0.f, 0.f, 0.f, 0.f};
    if (isA) {
        #pragma unroll
        for (int n = 0; n < 4; ++n) {
            int idx = tid + n * 288;
            if (idx < RW * IND)
                xr[n] = x[((size_t)(b0 + (idx >> 7)) * TT + 1) * IND + (idx & 127)];
        }
    }

    __syncthreads();
    asm volatile("barrier.cluster.arrive.aligned;" ::: "memory");
    asm volatile("barrier.cluster.wait.aligned;" ::: "memory");

    if (isA) {
        // =================== STAGE A : layer 0 ===================
        const float* WbA = g_W0q[rk] + (size_t)(kcA * 32) * WS0 + comboA * 4;
        for (int t = 0; t < TT; ++t) {
            const int pr = t & 1, pw = (t + 1) & 1;
            float* xh0r = xh0A + pr * XB0F;
            float* xh0w = xh0A + pw * XB0F;
            float* xh1c = xh1A + pr * XB1F;

            if (t >= 1)
                mbar_wait(sbase + MB_RDYA((t - 1) & 1) * 4, ((t - 1) >> 1) & 1);

            if (actA) {
                const float* Wp = WbA;
                const float* ab = xh0r + (kcA * 32) * 8;
                ull a0p0 = 0, a0p1 = 0, a0p2 = 0, a0p3 = 0;
                ull a1p0 = 0, a1p1 = 0, a1p2 = 0, a1p3 = 0;
                ull a2p0 = 0, a2p1 = 0, a2p2 = 0, a2p3 = 0;
                ull a3p0 = 0, a3p1 = 0, a3p2 = 0, a3p3 = 0;
                #pragma unroll 4
                for (int k = 0; k < 32; ++k) {
                    float4 wv = *(const float4*)(Wp + k * WS0);
                    ull w0 = pack2(wv.x, wv.x), w1 = pack2(wv.y, wv.y);
                    ull w2 = pack2(wv.z, wv.z), w3 = pack2(wv.w, wv.w);
                    ulonglong2 a03 = *(const ulonglong2*)(ab + k * 8);
                    ulonglong2 a47 = *(const ulonglong2*)(ab + k * 8 + 4);
                    a0p0 = fma2(w0, a03.x, a0p0); a0p1 = fma2(w0, a03.y, a0p1);
                    a0p2 = fma2(w0, a47.x, a0p2); a0p3 = fma2(w0, a47.y, a0p3);
                    a1p0 = fma2(w1, a03.x, a1p0); a1p1 = fma2(w1, a03.y, a1p1);
                    a1p2 = fma2(w1, a47.x, a1p2); a1p3 = fma2(w1, a47.y, a1p3);
                    a2p0 = fma2(w2, a03.x, a2p0); a2p1 = fma2(w2, a03.y, a2p1);
                    a2p2 = fma2(w2, a47.x, a2p2); a2p3 = fma2(w2, a47.y, a2p3);
                    a3p0 = fma2(w3, a03.x, a3p0); a3p1 = fma2(w3, a03.y, a3p1);
                    a3p2 = fma2(w3, a47.x, a3p2); a3p3 = fma2(w3, a47.y, a3p3);
                }
                // partials: ull layout [kc][mat][40j][4p]
                ull* PU = (ull*)partA + (((size_t)(kcA * 3 + matA) * 40 + jgA * 4) << 2);
                *(ulonglong2*)(PU + 0)  = make_ulonglong2(a0p0, a0p1);
                *(ulonglong2*)(PU + 2)  = make_ulonglong2(a0p2, a0p3);
                *(ulonglong2*)(PU + 4)  = make_ulonglong2(a1p0, a1p1);
                *(ulonglong2*)(PU + 6)  = make_ulonglong2(a1p2, a1p3);
                *(ulonglong2*)(PU + 8)  = make_ulonglong2(a2p0, a2p1);
                *(ulonglong2*)(PU + 10) = make_ulonglong2(a2p2, a2p3);
                *(ulonglong2*)(PU + 12) = make_ulonglong2(a3p0, a3p1);
                *(ulonglong2*)(PU + 14) = make_ulonglong2(a3p2, a3p3);
            }
            BARN(1, 288);

            if (t >= 2)
                mbar_wait(sbase + MB_CONB(t & 1) * 4, ((t - 2) >> 1) & 1);

            if (combA) {
                ull s1 = 0, s2 = 0, sc = 0;
                const ull* PU = (const ull*)partA;
                #pragma unroll
                for (int c = 0; c < 9; ++c) {
                    s1 = add2(s1, PU[((size_t)(c * 3 + 0) * 40 + cjA) * 4 + rpA]);
                    s2 = add2(s2, PU[((size_t)(c * 3 + 1) * 40 + cjA) * 4 + rpA]);
                    sc = add2(sc, PU[((size_t)(c * 3 + 2) * 40 + cjA) * 4 + rpA]);
                }
                float z1a, z1b, z2a, z2b, zca, zcb;
                unpack2(s1, z1a, z1b); unpack2(s2, z2a, z2b); unpack2(sc, zca, zcb);
                float ha = cfc_mix(z1a, z2a, zca, bA1, bA2, bAc);
                float hb = cfc_mix(z1b, z2b, zcb, bA1, bA2, bAc);
                ull u = pack2(ha, hb);
                const int jg = jb0 + cjA;
                const int oX = (IND + jg) * 8 + rpA * 2;
                const int oH = jg * 8 + rpA * 2;
                *(ull*)&xh0w[oX] = u;
                *(ull*)&xh1c[oH] = u;
                #pragma unroll
                for (unsigned r = 0; r < 4; ++r) {
                    if (r == rk) continue;
                    st_rank_u64(sbase + (OFF_XH0 + pw * XB0F + oX) * 4, r, u);
                    st_rank_u64(sbase + (OFF_XH1 + pr * XB1F + oH) * 4, r, u);
                }
            }
            // x restage + prefetch
            #pragma unroll
            for (int n = 0; n < 4; ++n) {
                int idx = tid + n * 288;
                if (idx < RW * IND)
                    xh0w[(idx & 127) * 8 + (idx >> 7)] = xr[n];
            }
            {
                int tn = t + 2; if (tn > TT - 1) tn = TT - 1;
                #pragma unroll
                for (int n = 0; n < 4; ++n) {
                    int idx = tid + n * 288;
                    if (idx < RW * IND)
                        xr[n] = x[((size_t)(b0 + (idx >> 7)) * TT + tn) * IND + (idx & 127)];
                }
            }
            BARN(1, 288);
            if (tid == 0) {
                cfence();
                arrive_all(sbase + MB_RDYA(t & 1) * 4, rk);
            }
        }
    } else if (isB) {
        // =================== STAGE B : layer 1 ===================
        const float* WbB = g_W1q[rk] + (size_t)(kcB * 52) * WS1 + comboB * 4;
        for (int t = 0; t < TT; ++t) {
            const int pr = t & 1, pw = (t + 1) & 1;
            float* xh1r = xh1A + pr * XB1F;
            float* xh1w = xh1A + pw * XB1F;
            float* xh2c = xh2A + pr * XB2F;

            mbar_wait(sbase + MB_RDYA(t & 1) * 4, (t >> 1) & 1);
            if (t >= 1)
                mbar_wait(sbase + MB_RDYB((t - 1) & 1) * 4, ((t - 1) >> 1) & 1);

            if (actB) {
                const float* Wp = WbB;
                const float* ab = xh1r + (kcB * 52) * 8;
                ull a0p0 = 0, a0p1 = 0, a0p2 = 0, a0p3 = 0;
                ull a1p0 = 0, a1p1 = 0, a1p2 = 0, a1p3 = 0;
                ull a2p0 = 0, a2p1 = 0, a2p2 = 0, a2p3 = 0;
                ull a3p0 = 0, a3p1 = 0, a3p2 = 0, a3p3 = 0;
                #pragma unroll 4
                for (int k = 0; k < 52; ++k) {
                    float4 wv = *(const float4*)(Wp + k * WS1);
                    ull w0 = pack2(wv.x, wv.x), w1 = pack2(wv.y, wv.y);
                    ull w2 = pack2(wv.z, wv.z), w3 = pack2(wv.w, wv.w);
                    ulonglong2 a03 = *(const ulonglong2*)(ab + k * 8);
                    ulonglong2 a47 = *(const ulonglong2*)(ab + k * 8 + 4);
                    a0p0 = fma2(w0, a03.x, a0p0); a0p1 = fma2(w0, a03.y, a0p1);
                    a0p2 = fma2(w0, a47.x, a0p2); a0p3 = fma2(w0, a47.y, a0p3);
                    a1p0 = fma2(w1, a03.x, a1p0); a1p1 = fma2(w1, a03.y, a1p1);
                    a1p2 = fma2(w1, a47.x, a1p2); a1p3 = fma2(w1, a47.y, a1p3);
                    a2p0 = fma2(w2, a03.x, a2p0); a2p1 = fma2(w2, a03.y, a2p1);
                    a2p2 = fma2(w2, a47.x, a2p2); a2p3 = fma2(w2, a47.y, a2p3);
                    a3p0 = fma2(w3, a03.x, a3p0); a3p1 = fma2(w3, a03.y, a3p1);
                    a3p2 = fma2(w3, a47.x, a3p2); a3p3 = fma2(w3, a47.y, a3p3);
                }
                ull* PU = (ull*)partB + (((size_t)(kcB * 3 + matB) * 28 + jgB * 4) << 2);
                *(ulonglong2*)(PU + 0)  = make_ulonglong2(a0p0, a0p1);
                *(ulonglong2*)(PU + 2)  = make_ulonglong2(a0p2, a0p3);
                *(ulonglong2*)(PU + 4)  = make_ulonglong2(a1p0, a1p1);
                *(ulonglong2*)(PU + 6)  = make_ulonglong2(a1p2, a1p3);
                *(ulonglong2*)(PU + 8)  = make_ulonglong2(a2p0, a2p1);
                *(ulonglong2*)(PU + 10) = make_ulonglong2(a2p2, a2p3);
                *(ulonglong2*)(PU + 12) = make_ulonglong2(a3p0, a3p1);
                *(ulonglong2*)(PU + 14) = make_ulonglong2(a3p2, a3p3);
            }
            BARN(2, 160);
            if (bt == 0)
                arrive_all(sbase + MB_CONB(t & 1) * 4, rk);
            if (t >= 2)
                mbar_wait(sbase + MB_CONC(t & 1) * 4, ((t - 2) >> 1) & 1);

            if (combB) {
                ull s1 = 0, s2 = 0, sc = 0;
                const ull* PU = (const ull*)partB;
                #pragma unroll
                for (int c = 0; c < 5; ++c) {
                    s1 = add2(s1, PU[((size_t)(c * 3 + 0) * 28 + cjB) * 4 + rpB]);
                    s2 = add2(s2, PU[((size_t)(c * 3 + 1) * 28 + cjB) * 4 + rpB]);
                    sc = add2(sc, PU[((size_t)(c * 3 + 2) * 28 + cjB) * 4 + rpB]);
                }
                float z1a, z1b, z2a, z2b, zca, zcb;
                unpack2(s1, z1a, z1b); unpack2(s2, z2a, z2b); unpack2(sc, zca, zcb);
                float ha = cfc_mix(z1a, z2a, zca, bB1, bB2, bBc);
                float hb = cfc_mix(z1b, z2b, zcb, bB1, bB2, bBc);
                ull u = pack2(ha, hb);
                const int jg = jb1 + cjB;
                const int oH = (NI + jg) * 8 + rpB * 2;
                const int o2 = jg * 8 + rpB * 2;
                *(ull*)&xh1w[oH] = u;
                *(ull*)&xh2c[o2] = u;
                #pragma unroll
                for (unsigned r = 0; r < 4; ++r) {
                    if (r == rk) continue;
                    st_rank_u64(sbase + (OFF_XH1 + pw * XB1F + oH) * 4, r, u);
                    st_rank_u64(sbase + (OFF_XH2 + pr * XB2F + o2) * 4, r, u);
                }
            }
            BARN(2, 160);
            if (bt == 0) {
                cfence();
                arrive_all(sbase + MB_RDYB(t & 1) * 4, rk);
            }
        }
    } else {
        // =================== STAGE C : layer 2 ===================
        for (int t = 0; t < TT; ++t) {
            const int pr = t & 1, pw = (t + 1) & 1;
            float* xh2r = xh2A + pr * XB2F;
            float* xh2w = xh2A + pw * XB2F;

            mbar_wait(sbase + MB_RDYB(t & 1) * 4, (t >> 1) & 1);

            ull p0 = 0, p1 = 0, p2 = 0, p3 = 0;
            if (actC) {
                const float* W = sw2 + matC * (CAT2 * 8) + jC;
                #pragma unroll 4
                for (int k = 0; k < CAT2; ++k) {
                    float w = W[k * 8];
                    ull ww = pack2(w, w);
                    ulonglong2 a03 = *(const ulonglong2*)(xh2r + k * 8);
                    ulonglong2 a47 = *(const ulonglong2*)(xh2r + k * 8 + 4);
                    p0 = fma2(ww, a03.x, p0); p1 = fma2(ww, a03.y, p1);
                    p2 = fma2(ww, a47.x, p2); p3 = fma2(ww, a47.y, p3);
                }
            }
            __syncwarp();
            if (ct == 0)
                arrive_all(sbase + MB_CONC(t & 1) * 4, rk);
            ull q0 = __shfl_sync(0xffffffffu, p0, 8 + jC);
            ull q1 = __shfl_sync(0xffffffffu, p1, 8 + jC);
            ull q2 = __shfl_sync(0xffffffffu, p2, 8 + jC);
            ull q3 = __shfl_sync(0xffffffffu, p3, 8 + jC);
            ull r0 = __shfl_sync(0xffffffffu, p0, 16 + jC);
            ull r1 = __shfl_sync(0xffffffffu, p1, 16 + jC);
            ull r2 = __shfl_sync(0xffffffffu, p2, 16 + jC);
            ull r3 = __shfl_sync(0xffffffffu, p3, 16 + jC);
            if (ct < 8) {
                float a1[8], a2[8], ac[8];
                unpack2(p0, a1[0], a1[1]); unpack2(p1, a1[2], a1[3]);
                unpack2(p2, a1[4], a1[5]); unpack2(p3, a1[6], a1[7]);
                unpack2(q0, a2[0], a2[1]); unpack2(q1, a2[2], a2[3]);
                unpack2(q2, a2[4], a2[5]); unpack2(q3, a2[6], a2[7]);
                unpack2(r0, ac[0], ac[1]); unpack2(r1, ac[2], ac[3]);
                unpack2(r2, ac[4], ac[5]); unpack2(r3, ac[6], ac[7]);
                #pragma unroll
                for (int r = 0; r < 8; ++r) {
                    float h = cfc_mix(a1[r], a2[r], ac[r], bC1, bC2, bCc);
                    xh2w[(NCC + jC) * 8 + r] = h;
                    if (rk == 0)
                        out[((size_t)(b0 + r) * TT + t) * NM + jC] = tanhf(h);
                }
            }
            __syncwarp();
        }
    }

    __syncthreads();
    asm volatile("barrier.cluster.arrive.aligned;" ::: "memory");
    asm volatile("barrier.cluster.wait.aligned;" ::: "memory");
    cfence();

    if (write_h && rk == 0) {
        // TT even: final states in buffer 0
        size_t base = (size_t)BB * TT * NM;
        for (int jt = tid; jt < 256; jt += NTH) {
            #pragma unroll
            for (int r = 0; r < RW; ++r) {
                float v;
                if (jt < NI)            v = xh0A[(IND + jt) * 8 + r];
                else if (jt < NI + NCC) v = xh1A[(NI + (jt - NI)) * 8 + r];
                else                    v = xh2A[(NCC + (jt - NI - NCC)) * 8 + r];
                out[base + (size_t)(b0 + r) * 256 + jt] = v;
            }
        }
    }
    asm volatile("barrier.cluster.arrive.aligned;" ::: "memory");
    asm volatile("barrier.cluster.wait.aligned;" ::: "memory");
}

// ---------------------------------------------------------------------------
extern "C" void kernel_launch(void* const* d_in, const int* in_sizes, int n_in,
                              void* d_out, int out_size)
{
    const float *x, *dt;
    const float *w1[3], *b1[3], *w2[3], *b2[3], *wa[3], *ba[3], *wb[3], *bb[3];
    const int   *m[3];

    if (in_sizes[0] == BB * TT * IND) {
        x  = (const float*)d_in[0];
        dt = (const float*)d_in[1];
        for (int l = 0; l < 3; l++) {
            int base = 2 + 9 * l;
            w1[l] = (const float*)d_in[base + 0];
            b1[l] = (const float*)d_in[base + 1];
            w2[l] = (const float*)d_in[base + 2];
            b2[l] = (const float*)d_in[base + 3];
            wa[l] = (const float*)d_in[base + 4];
            ba[l] = (const float*)d_in[base + 5];
            wb[l] = (const float*)d_in[base + 6];
            bb[l] = (const float*)d_in[base + 7];
            m[l]  = (const int*)  d_in[base + 8];
        }
    } else {
        for (int l = 0; l < 3; l++) {
            int base = 9 * l;
            w1[l] = (const float*)d_in[base + 0];
            w2[l] = (const float*)d_in[base + 1];
            wa[l] = (const float*)d_in[base + 2];
            wb[l] = (const float*)d_in[base + 3];
            b1[l] = (const float*)d_in[base + 4];
            b2[l] = (const float*)d_in[base + 5];
            ba[l] = (const float*)d_in[base + 6];
            bb[l] = (const float*)d_in[base + 7];
            m[l]  = (const int*)  d_in[base + 8];
        }
        x  = (const float*)d_in[27];
        dt = (const float*)d_in[28];
    }

    cfc_precompute_kernel<<<148, 256>>>(
        w1[0], w2[0], wa[0], wb[0], ba[0], bb[0], m[0],
        w1[1], w2[1], wa[1], wb[1], ba[1], bb[1], m[1],
        w1[2], w2[2], wa[2], wb[2], ba[2], bb[2], m[2],
        dt);

    cudaFuncSetAttribute(cfc_main_kernel,
                         cudaFuncAttributeMaxDynamicSharedMemorySize, SMEM_BYTES);

    int write_h = (out_size >= BB * TT * NM + BB * 256) ? 1 : 0;
    cfc_main_kernel<<<(BB / RW) * CL, NTH, SMEM_BYTES>>>(
        x, b1[0], b2[0], b1[1], b2[1], b1[2], b2[2],
        (float*)d_out, write_h);
}

// round 14
// speedup vs baseline: 1.4624x; 1.4624x over previous
#include <cuda_runtime.h>
#include <cuda_fp16.h>
#include <math.h>

typedef unsigned long long ull;

// Problem constants
#define BB   256
#define TT   512
#define IND  128
#define NI   149
#define NCC  99
#define NM   8
#define CAT0 277
#define CAT1 248
#define CAT2 107
#define K0P  280          // 5 chunks x 56
#define K1P  252          // 4 chunks x 63
#define ROWS 4
#define NTH  480
#define RS0  240          // fused row stride layer0 (3*76=228 active), in halfs
#define RS1  160          // fused row stride layer1 (3*52=156 active), in halfs

// SMEM layout (float offsets)
#define XB0F  2240        // 280*8
#define XB1F  2016        // 252*8
#define XB2F  448         // 112*4
#define OFF_XH0   0
#define OFF_XH1   4480
#define OFF_XH2   8512
#define OFF_PARTA 9408    // 5*3*4*80 = 4800
#define OFF_PARTB 14208   // 4*3*4*56 = 2688
#define OFF_SW2   16896   // 3*107*8 = 2568
#define OFF_MBAR  19464   // 8 mbarriers = 16 floats
#define SMEM_FLOATS 19480
#define SMEM_BYTES  (SMEM_FLOATS * 4)

#define MB_RDYA(s)  (OFF_MBAR + 0 + 2*(s))
#define MB_CONB(s)  (OFF_MBAR + 4 + 2*(s))
#define MB_RDYB(s)  (OFF_MBAR + 8 + 2*(s))
#define MB_CONC(s)  (OFF_MBAR + 12 + 2*(s))

// Fused per-rank weight arrays, fp16 storage (fp32 accumulate in kernel).
// One k-row = [mat0 j0..75 | mat1 ... | mat2 ...] so warp-consecutive combos
// load contiguous bytes (LDG.64 x 32 = 256B contiguous).
__device__ __half g_W0h[2][K0P * RS0];
__device__ __half g_W1h[2][K1P * RS1];
__device__ float  g_W2[3][CAT2 * 8];
__device__ float  g_bc[NI + NCC + NM];

// ---------------------------------------------------------------------------
__global__ void cfc_precompute_kernel(
    const float* __restrict__ w1_0, const float* __restrict__ w2_0,
    const float* __restrict__ wa_0, const float* __restrict__ wb_0,
    const float* __restrict__ ba_0, const float* __restrict__ bb_0,
    const int*   __restrict__ m0,
    const float* __restrict__ w1_1, const float* __restrict__ w2_1,
    const float* __restrict__ wa_1, const float* __restrict__ wb_1,
    const float* __restrict__ ba_1, const float* __restrict__ bb_1,
    const int*   __restrict__ m1,
    const float* __restrict__ w1_2, const float* __restrict__ w2_2,
    const float* __restrict__ wa_2, const float* __restrict__ wb_2,
    const float* __restrict__ ba_2, const float* __restrict__ bb_2,
    const int*   __restrict__ m2,
    const float* __restrict__ dt)
{
    const float ts = dt[0];
    const int idx    = blockIdx.x * blockDim.x + threadIdx.x;
    const int stride = gridDim.x * blockDim.x;

    // layer-0 fused: rank r, row k, col c: c<228 -> mat=c/76, jl=c%76
    for (int i = idx; i < 2 * K0P * RS0; i += stride) {
        int r = i / (K0P * RS0), rem = i - r * (K0P * RS0);
        int k = rem / RS0, c = rem - k * RS0;
        float v = 0.f;
        if (c < 228 && k < CAT0) {
            int mat = c / 76, jl = c - mat * 76;
            int jb = r ? 76 : 0, nj = r ? 73 : 76;
            if (jl < nj) {
                int j = jb + jl;
                int src = j * CAT0 + k;
                float mm = (float)m0[src];
                if (mat == 0)      v = w1_0[src] * mm;
                else if (mat == 1) v = w2_0[src] * mm;
                else               v = ts * wa_0[src] + wb_0[src];
            }
        }
        g_W0h[r][k * RS0 + c] = __float2half(v);
    }
    // layer-1 fused: c<156 -> mat=c/52, jl=c%52
    for (int i = idx; i < 2 * K1P * RS1; i += stride) {
        int r = i / (K1P * RS1), rem = i - r * (K1P * RS1);
        int k = rem / RS1, c = rem - k * RS1;
        float v = 0.f;
        if (c < 156 && k < CAT1) {
            int mat = c / 52, jl = c - mat * 52;
            int jb = r ? 52 : 0, nj = r ? 47 : 52;
            if (jl < nj) {
                int j = jb + jl;
                int src = j * CAT1 + k;
                float mm = (float)m1[src];
                if (mat == 0)      v = w1_1[src] * mm;
                else if (mat == 1) v = w2_1[src] * mm;
                else               v = ts * wa_1[src] + wb_1[src];
            }
        }
        g_W1h[r][k * RS1 + c] = __float2half(v);
    }
    for (int i = idx; i < CAT2 * 8; i += stride) {
        int k = i / 8, j = i - k * 8;
        int src = j * CAT2 + k;
        float mm = (float)m2[src];
        g_W2[0][i] = w1_2[src] * mm;
        g_W2[1][i] = w2_2[src] * mm;
        g_W2[2][i] = ts * wa_2[src] + wb_2[src];
    }
    for (int j = idx; j < NI;  j += stride) g_bc[j]            = ts * ba_0[j] + bb_0[j];
    for (int j = idx; j < NCC; j += stride) g_bc[NI + j]       = ts * ba_1[j] + bb_1[j];
    for (int j = idx; j < NM;  j += stride) g_bc[NI + NCC + j] = ts * ba_2[j] + bb_2[j];
}

// ---------------------------------------------------------------------------
__device__ __forceinline__ ull pack2(float a, float b) {
    ull r; asm("mov.b64 %0, {%1, %2};" : "=l"(r) : "f"(a), "f"(b)); return r;
}
__device__ __forceinline__ void unpack2(ull v, float& a, float& b) {
    asm("mov.b64 {%0, %1}, %2;" : "=f"(a), "=f"(b) : "l"(v));
}
__device__ __forceinline__ ull fma2(ull a, ull b, ull c) {
    ull d; asm("fma.rn.f32x2 %0, %1, %2, %3;" : "=l"(d) : "l"(a), "l"(b), "l"(c)); return d;
}
// Load 4 fp16 weights (8B) and expand to two f32x2 pairs (wj0,wj1),(wj2,wj3)
__device__ __forceinline__ void ldw4_h(const __half* p, ull& wx, ull& wy) {
    unsigned lo, hi;
    asm("ld.global.nc.v2.u32 {%0, %1}, [%2];" : "=r"(lo), "=r"(hi) : "l"(p));
    float2 f01 = __half22float2(*(__half2*)&lo);
    float2 f23 = __half22float2(*(__half2*)&hi);
    wx = pack2(f01.x, f01.y);
    wy = pack2(f23.x, f23.y);
}
__device__ __forceinline__ float sigmoidf_(float z) { return 1.0f / (1.0f + expf(-z)); }
__device__ __forceinline__ float cfc_mix(float a1, float a2, float ac,
                                         float b1, float b2, float bc) {
    float ff1 = tanhf(a1 + b1);
    float ff2 = tanhf(a2 + b2);
    float ti  = sigmoidf_(ac + bc);
    return ff1 + ti * (ff2 - ff1);
}
__device__ __forceinline__ unsigned smem_u32(const void* p) {
    unsigned a;
    asm("{ .reg .u64 t; cvta.to.shared.u64 t, %1; cvt.u32.u64 %0, t; }" : "=r"(a) : "l"(p));
    return a;
}
__device__ __forceinline__ void mbar_init(unsigned addr, unsigned count) {
    asm volatile("mbarrier.init.shared.b64 [%0], %1;" :: "r"(addr), "r"(count) : "memory");
}
__device__ __forceinline__ void mbar_wait(unsigned addr, unsigned parity) {
    unsigned done = 0;
    do {
        asm volatile(
            "{\n\t.reg .pred P;\n\t"
            "mbarrier.try_wait.parity.acquire.cluster.shared::cta.b64 P, [%1], %2, 0x989680;\n\t"
            "selp.b32 %0, 1, 0, P;\n\t}"
            : "=r"(done) : "r"(addr), "r"(parity) : "memory");
    } while (!done);
}
__device__ __forceinline__ void mbar_arrive_local(unsigned addr) {
    asm volatile("mbarrier.arrive.release.cluster.shared::cta.b64 _, [%0];"
                 :: "r"(addr) : "memory");
}
__device__ __forceinline__ void mbar_arrive_peer(unsigned addr, unsigned peer) {
    asm volatile(
        "{\n\t.reg .b32 ra;\n\t"
        "mapa.shared::cluster.u32 ra, %0, %1;\n\t"
        "mbarrier.arrive.release.cluster.shared::cluster.b64 _, [ra];\n\t}"
        :: "r"(addr), "r"(peer) : "memory");
}
__device__ __forceinline__ void cfence() {
    asm volatile("fence.acq_rel.cluster;" ::: "memory");
}
__device__ __forceinline__ void st_peer_u64(unsigned addr, unsigned peer, ull v) {
    asm volatile(
        "{\n\t.reg .b32 ra;\n\t"
        "mapa.shared::cluster.u32 ra, %0, %1;\n\t"
        "st.shared::cluster.u64 [ra], %2;\n\t}"
        :: "r"(addr), "r"(peer), "l"(v) : "memory");
}
__device__ __forceinline__ void st_peer_u32(unsigned addr, unsigned peer, float v) {
    asm volatile(
        "{\n\t.reg .b32 ra;\n\t"
        "mapa.shared::cluster.u32 ra, %0, %1;\n\t"
        "st.shared::cluster.f32 [ra], %2;\n\t}"
        :: "r"(addr), "r"(peer), "f"(v) : "memory");
}
#define BARN(id, n) asm volatile("bar.sync %0, %1;" :: "r"(id), "r"(n) : "memory")

// ---------------------------------------------------------------------------
// Pipelined kernel (R10/R11 structure): 64 clusters x 2 CTAs, 4 rows/cluster,
// j split across pair; warps 0-8 = layer0 (A), 9-13 = layer1 (B),
// warp 14 = layer2 (C). fp16 weight streams, fp32 accumulate.
// ---------------------------------------------------------------------------
__global__ __launch_bounds__(NTH, 1) __cluster_dims__(2, 1, 1)
void cfc_main_kernel(
    const float* __restrict__ x,
    const float* __restrict__ b1_0, const float* __restrict__ b2_0,
    const float* __restrict__ b1_1, const float* __restrict__ b2_1,
    const float* __restrict__ b1_2, const float* __restrict__ b2_2,
    float* __restrict__ out, int write_h)
{
    extern __shared__ float sm[];
    float* xh0A  = sm + OFF_XH0;
    float* xh1A  = sm + OFF_XH1;
    float* xh2A  = sm + OFF_XH2;
    float* partA = sm + OFF_PARTA;
    float* partB = sm + OFF_PARTB;
    float* sw2   = sm + OFF_SW2;

    const int tid = threadIdx.x;
    unsigned rank;
    asm("mov.u32 %0, %%cluster_ctarank;" : "=r"(rank));
    const unsigned peer = rank ^ 1u;
    const int b0 = (blockIdx.x >> 1) * ROWS;

    const int nj0 = rank ? 73 : 76;
    const int jb0 = rank ? 76 : 0;
    const int nj1 = rank ? 47 : 52;
    const int jb1 = rank ? 52 : 0;

    const unsigned sbase = smem_u32(sm);

    const bool isA = (tid < 288);
    const bool isB = (tid >= 288 && tid < 448);

    // stage A: 57 combos (mat*19+jg) x 5 kc(56)
    const int at = tid;
    const int comboA = at % 57, kcA = at / 57;
    const int matA = comboA / 19, jgA = comboA % 19;
    const bool actA = isA && (at < 285);
    const bool combA = isA && (at < 152);
    const int cjA = at >> 1, crA = (at & 1) * 2;

    // stage B: 39 combos (mat*13+jg) x 4 kc(63)
    const int bt = tid - 288;
    const int comboB = bt % 39, kcB = bt / 39;
    const int matB = comboB / 13, jgB = comboB % 13;
    const bool actB = isB && (bt < 156);
    const bool combB = isB && (bt < 104);
    const int cjB = bt >> 1, crB = (bt & 1) * 2;

    // stage C
    const int ct = tid - 448;
    const int matC = ct >> 3, jC = ct & 7;
    const bool actC = (tid >= 448) && (ct < 24);

    // ---- prologue ----
    for (int i = tid; i < 2 * XB0F; i += NTH) xh0A[i] = 0.f;
    for (int i = tid; i < 2 * XB1F; i += NTH) xh1A[i] = 0.f;
    for (int i = tid; i < 2 * XB2F; i += NTH) xh2A[i] = 0.f;
    for (int i = tid; i < 3 * CAT2 * 8; i += NTH) sw2[i] = ((const float*)g_W2)[i];
    if (tid == 0) {
        for (int s = 0; s < 2; ++s) {
            mbar_init(sbase + MB_RDYA(s) * 4, 2);
            mbar_init(sbase + MB_CONB(s) * 4, 2);
            mbar_init(sbase + MB_RDYB(s) * 4, 2);
            mbar_init(sbase + MB_CONC(s) * 4, 2);
        }
    }

    float bA1 = 0.f, bA2 = 0.f, bAc = 0.f;
    if (combA && cjA < nj0) { bA1 = b1_0[jb0 + cjA]; bA2 = b2_0[jb0 + cjA]; bAc = g_bc[jb0 + cjA]; }
    float bB1 = 0.f, bB2 = 0.f, bBc = 0.f;
    if (combB && cjB < nj1) { bB1 = b1_1[jb1 + cjB]; bB2 = b2_1[jb1 + cjB]; bBc = g_bc[NI + jb1 + cjB]; }
    float bC1 = 0.f, bC2 = 0.f, bCc = 0.f;
    if (tid >= 448) { bC1 = b1_2[jC]; bC2 = b2_2[jC]; bCc = g_bc[NI + NCC + jC]; }

    for (int i = tid; i < ROWS * IND; i += NTH) {
        int r = i >> 7, k = i & 127;
        float v = x[((size_t)(b0 + r) * TT + 0) * IND + k];
        *(ull*)&xh0A[k * 8 + r * 2] = pack2(v, v);
    }
    float xr0 = 0.f, xr1 = 0.f;
    const int i0 = tid, i1 = tid + 288;
    if (isA) {
        xr0 = x[((size_t)(b0 + (i0 >> 7)) * TT + 1) * IND + (i0 & 127)];
        if (i1 < ROWS * IND)
            xr1 = x[((size_t)(b0 + (i1 >> 7)) * TT + 1) * IND + (i1 & 127)];
    }

    __syncthreads();
    asm volatile("barrier.cluster.arrive.aligned;" ::: "memory");
    asm volatile("barrier.cluster.wait.aligned;" ::: "memory");

    if (isA) {
        // =================== STAGE A : layer 0 ===================
        const __half* WbA = g_W0h[rank] + (size_t)(kcA * 56) * RS0 + comboA * 4;
        for (int t = 0; t < TT; ++t) {
            const int pr = t & 1, pw = (t + 1) & 1;
            float* xh0r = xh0A + pr * XB0F;
            float* xh0w = xh0A + pw * XB0F;
            float* xh1c = xh1A + pr * XB1F;

            if (t >= 1)
                mbar_wait(sbase + MB_RDYA((t - 1) & 1) * 4, ((t - 1) >> 1) & 1);

            if (actA) {
                const __half* Wp = WbA;
                const float* ab = xh0r + (kcA * 56) * 8;
                ull aA0 = 0, aB0 = 0, aA1 = 0, aB1 = 0;
                ull aA2 = 0, aB2 = 0, aA3 = 0, aB3 = 0;
                #pragma unroll 8
                for (int k = 0; k < 56; ++k) {
                    ull wx, wy;
                    ldw4_h(Wp + (size_t)k * RS0, wx, wy);
                    ulonglong2 d01 = *(const ulonglong2*)(ab + k * 8);
                    ulonglong2 d23 = *(const ulonglong2*)(ab + k * 8 + 4);
                    aA0 = fma2(wx, d01.x, aA0); aB0 = fma2(wy, d01.x, aB0);
                    aA1 = fma2(wx, d01.y, aA1); aB1 = fma2(wy, d01.y, aB1);
                    aA2 = fma2(wx, d23.x, aA2); aB2 = fma2(wy, d23.x, aB2);
                    aA3 = fma2(wx, d23.y, aA3); aB3 = fma2(wy, d23.y, aB3);
                }
                float* P = partA + (size_t)((kcA * 3 + matA) * 4) * 80 + jgA * 4;
                *(ulonglong2*)(P)       = make_ulonglong2(aA0, aB0);
                *(ulonglong2*)(P + 80)  = make_ulonglong2(aA1, aB1);
                *(ulonglong2*)(P + 160) = make_ulonglong2(aA2, aB2);
                *(ulonglong2*)(P + 240) = make_ulonglong2(aA3, aB3);
            }
            BARN(1, 288);

            if (t >= 2)
                mbar_wait(sbase + MB_CONB(t & 1) * 4, ((t - 2) >> 1) & 1);

            if (combA && cjA < nj0) {
                const int r0 = crA, r1 = crA + 1;
                float a1r0 = 0, a1r1 = 0, a2r0 = 0, a2r1 = 0, acr0 = 0, acr1 = 0;
                #pragma unroll
                for (int c = 0; c < 5; ++c) {
                    const float* P = partA + (size_t)(c * 12) * 80;
                    a1r0 += P[(0 * 4 + r0) * 80 + cjA];
                    a1r1 += P[(0 * 4 + r1) * 80 + cjA];
                    a2r0 += P[(1 * 4 + r0) * 80 + cjA];
                    a2r1 += P[(1 * 4 + r1) * 80 + cjA];
                    acr0 += P[(2 * 4 + r0) * 80 + cjA];
                    acr1 += P[(2 * 4 + r1) * 80 + cjA];
                }
                float h0v = cfc_mix(a1r0, a2r0, acr0, bA1, bA2, bAc);
                float h1v = cfc_mix(a1r1, a2r1, acr1, bA1, bA2, bAc);
                ull u0 = pack2(h0v, h0v), u1 = pack2(h1v, h1v);
                const int jg = jb0 + cjA;
                const int oX = (IND + jg) * 8;
                const int oH = jg * 8;
                *(ull*)&xh0w[oX + r0 * 2] = u0;
                *(ull*)&xh0w[oX + r1 * 2] = u1;
                *(ull*)&xh1c[oH + r0 * 2] = u0;
                *(ull*)&xh1c[oH + r1 * 2] = u1;
                st_peer_u64(sbase + (OFF_XH0 + pw * XB0F + oX + r0 * 2) * 4, peer, u0);
                st_peer_u64(sbase + (OFF_XH0 + pw * XB0F + oX + r1 * 2) * 4, peer, u1);
                st_peer_u64(sbase + (OFF_XH1 + pr * XB1F + oH + r0 * 2) * 4, peer, u0);
                st_peer_u64(sbase + (OFF_XH1 + pr * XB1F + oH + r1 * 2) * 4, peer, u1);
            }
            *(ull*)&xh0w[(i0 & 127) * 8 + (i0 >> 7) * 2] = pack2(xr0, xr0);
            if (i1 < ROWS * IND)
                *(ull*)&xh0w[(i1 & 127) * 8 + (i1 >> 7) * 2] = pack2(xr1, xr1);
            {
                int tn = t + 2; if (tn > TT - 1) tn = TT - 1;
                xr0 = x[((size_t)(b0 + (i0 >> 7)) * TT + tn) * IND + (i0 & 127)];
                if (i1 < ROWS * IND)
                    xr1 = x[((size_t)(b0 + (i1 >> 7)) * TT + tn) * IND + (i1 & 127)];
            }
            BARN(1, 288);
            if (tid == 0) {
                cfence();
                mbar_arrive_local(sbase + MB_RDYA(t & 1) * 4);
                mbar_arrive_peer(sbase + MB_RDYA(t & 1) * 4, peer);
            }
        }
    } else if (isB) {
        // =================== STAGE B : layer 1 ===================
        const __half* WbB = g_W1h[rank] + (size_t)(kcB * 63) * RS1 + comboB * 4;
        for (int t = 0; t < TT; ++t) {
            const int pr = t & 1, pw = (t + 1) & 1;
            float* xh1r = xh1A + pr * XB1F;
            float* xh1w = xh1A + pw * XB1F;
            float* xh2c = xh2A + pr * XB2F;

            mbar_wait(sbase + MB_RDYA(t & 1) * 4, (t >> 1) & 1);
            if (t >= 1)
                mbar_wait(sbase + MB_RDYB((t - 1) & 1) * 4, ((t - 1) >> 1) & 1);

            if (actB) {
                const __half* Wp = WbB;
                const float* ab = xh1r + (kcB * 63) * 8;
                ull aA0 = 0, aB0 = 0, aA1 = 0, aB1 = 0;
                ull aA2 = 0, aB2 = 0, aA3 = 0, aB3 = 0;
                #pragma unroll 7
                for (int k = 0; k < 63; ++k) {
                    ull wx, wy;
                    ldw4_h(Wp + (size_t)k * RS1, wx, wy);
                    ulonglong2 d01 = *(const ulonglong2*)(ab + k * 8);
                    ulonglong2 d23 = *(const ulonglong2*)(ab + k * 8 + 4);
                    aA0 = fma2(wx, d01.x, aA0); aB0 = fma2(wy, d01.x, aB0);
                    aA1 = fma2(wx, d01.y, aA1); aB1 = fma2(wy, d01.y, aB1);
                    aA2 = fma2(wx, d23.x, aA2); aB2 = fma2(wy, d23.x, aB2);
                    aA3 = fma2(wx, d23.y, aA3); aB3 = fma2(wy, d23.y, aB3);
                }
                float* P = partB + (size_t)((kcB * 3 + matB) * 4) * 56 + jgB * 4;
                *(ulonglong2*)(P)       = make_ulonglong2(aA0, aB0);
                *(ulonglong2*)(P + 56)  = make_ulonglong2(aA1, aB1);
                *(ulonglong2*)(P + 112) = make_ulonglong2(aA2, aB2);
                *(ulonglong2*)(P + 168) = make_ulonglong2(aA3, aB3);
            }
            BARN(2, 160);
            if (bt == 0) {
                mbar_arrive_local(sbase + MB_CONB(t & 1) * 4);
                mbar_arrive_peer(sbase + MB_CONB(t & 1) * 4, peer);
            }
            if (t >= 2)
                mbar_wait(sbase + MB_CONC(t & 1) * 4, ((t - 2) >> 1) & 1);

            if (combB && cjB < nj1) {
                const int r0 = crB, r1 = crB + 1;
                float a1r0 = 0, a1r1 = 0, a2r0 = 0, a2r1 = 0, acr0 = 0, acr1 = 0;
                #pragma unroll
                for (int c = 0; c < 4; ++c) {
                    const float* P = partB + (size_t)(c * 12) * 56;
                    a1r0 += P[(0 * 4 + r0) * 56 + cjB];
                    a1r1 += P[(0 * 4 + r1) * 56 + cjB];
                    a2r0 += P[(1 * 4 + r0) * 56 + cjB];
                    a2r1 += P[(1 * 4 + r1) * 56 + cjB];
                    acr0 += P[(2 * 4 + r0) * 56 + cjB];
                    acr1 += P[(2 * 4 + r1) * 56 + cjB];
                }
                float h0v = cfc_mix(a1r0, a2r0, acr0, bB1, bB2, bBc);
                float h1v = cfc_mix(a1r1, a2r1, acr1, bB1, bB2, bBc);
                ull u0 = pack2(h0v, h0v), u1 = pack2(h1v, h1v);
                const int jg = jb1 + cjB;
                const int oH = (NI + jg) * 8;
                const int o2 = jg * 4;
                *(ull*)&xh1w[oH + r0 * 2] = u0;
                *(ull*)&xh1w[oH + r1 * 2] = u1;
                xh2c[o2 + r0] = h0v;
                xh2c[o2 + r1] = h1v;
                st_peer_u64(sbase + (OFF_XH1 + pw * XB1F + oH + r0 * 2) * 4, peer, u0);
                st_peer_u64(sbase + (OFF_XH1 + pw * XB1F + oH + r1 * 2) * 4, peer, u1);
                st_peer_u32(sbase + (OFF_XH2 + pr * XB2F + o2 + r0) * 4, peer, h0v);
                st_peer_u32(sbase + (OFF_XH2 + pr * XB2F + o2 + r1) * 4, peer, h1v);
            }
            BARN(2, 160);
            if (bt == 0) {
                cfence();
                mbar_arrive_local(sbase + MB_RDYB(t & 1) * 4);
                mbar_arrive_peer(sbase + MB_RDYB(t & 1) * 4, peer);
            }
        }
    } else {
        // =================== STAGE C : layer 2 ===================
        for (int t = 0; t < TT; ++t) {
            const int pr = t & 1, pw = (t + 1) & 1;
            float* xh2r = xh2A + pr * XB2F;
            float* xh2w = xh2A + pw * XB2F;

            mbar_wait(sbase + MB_RDYB(t & 1) * 4, (t >> 1) & 1);

            ull acc01 = 0, acc23 = 0;
            if (actC) {
                const float* W = sw2 + matC * (CAT2 * 8) + jC;
                #pragma unroll 4
                for (int k = 0; k < CAT2; ++k) {
                    float w = W[k * 8];
                    ull ww = pack2(w, w);
                    ulonglong2 u = *(const ulonglong2*)(xh2r + k * 4);
                    acc01 = fma2(ww, u.x, acc01);
                    acc23 = fma2(ww, u.y, acc23);
                }
            }
            __syncwarp();
            if (ct == 0) {
                mbar_arrive_local(sbase + MB_CONC(t & 1) * 4);
                mbar_arrive_peer(sbase + MB_CONC(t & 1) * 4, peer);
            }
            ull m1_01 = __shfl_sync(0xffffffffu, acc01, 8 + jC);
            ull m1_23 = __shfl_sync(0xffffffffu, acc23, 8 + jC);
            ull m2_01 = __shfl_sync(0xffffffffu, acc01, 16 + jC);
            ull m2_23 = __shfl_sync(0xffffffffu, acc23, 16 + jC);
            if (ct < 8) {
                float a1[4], a2[4], ac[4];
                unpack2(acc01, a1[0], a1[1]); unpack2(acc23, a1[2], a1[3]);
                unpack2(m1_01, a2[0], a2[1]); unpack2(m1_23, a2[2], a2[3]);
                unpack2(m2_01, ac[0], ac[1]); unpack2(m2_23, ac[2], ac[3]);
                #pragma unroll
                for (int r = 0; r < 4; ++r) {
                    float h = cfc_mix(a1[r], a2[r], ac[r], bC1, bC2, bCc);
                    xh2w[(NCC + jC) * 4 + r] = h;
                    if (rank == 0)
                        out[((size_t)(b0 + r) * TT + t) * NM + jC] = tanhf(h);
                }
            }
            __syncwarp();
        }
    }

    __syncthreads();
    asm volatile("barrier.cluster.arrive.aligned;" ::: "memory");
    asm volatile("barrier.cluster.wait.aligned;" ::: "memory");
    cfence();

    if (write_h && rank == 0) {
        size_t base = (size_t)BB * TT * NM;
        for (int jt = tid; jt < 256; jt += NTH) {
            #pragma unroll
            for (int r = 0; r < 4; ++r) {
                float v;
                if (jt < NI)            v = xh0A[(IND + jt) * 8 + r * 2];
                else if (jt < NI + NCC) v = xh1A[(NI + (jt - NI)) * 8 + r * 2];
                else                    v = xh2A[(NCC + (jt - NI - NCC)) * 4 + r];
                out[base + (size_t)(b0 + r) * 256 + jt] = v;
            }
        }
    }
    asm volatile("barrier.cluster.arrive.aligned;" ::: "memory");
    asm volatile("barrier.cluster.wait.aligned;" ::: "memory");
}

// ---------------------------------------------------------------------------
extern "C" void kernel_launch(void* const* d_in, const int* in_sizes, int n_in,
                              void* d_out, int out_size)
{
    const float *x, *dt;
    const float *w1[3], *b1[3], *w2[3], *b2[3], *wa[3], *ba[3], *wb[3], *bb[3];
    const int   *m[3];

    if (in_sizes[0] == BB * TT * IND) {
        x  = (const float*)d_in[0];
        dt = (const float*)d_in[1];
        for (int l = 0; l < 3; l++) {
            int base = 2 + 9 * l;
            w1[l] = (const float*)d_in[base + 0];
            b1[l] = (const float*)d_in[base + 1];
            w2[l] = (const float*)d_in[base + 2];
            b2[l] = (const float*)d_in[base + 3];
            wa[l] = (const float*)d_in[base + 4];
            ba[l] = (const float*)d_in[base + 5];
            wb[l] = (const float*)d_in[base + 6];
            bb[l] = (const float*)d_in[base + 7];
            m[l]  = (const int*)  d_in[base + 8];
        }
    } else {
        for (int l = 0; l < 3; l++) {
            int base = 9 * l;
            w1[l] = (const float*)d_in[base + 0];
            w2[l] = (const float*)d_in[base + 1];
            wa[l] = (const float*)d_in[base + 2];
            wb[l] = (const float*)d_in[base + 3];
            b1[l] = (const float*)d_in[base + 4];
            b2[l] = (const float*)d_in[base + 5];
            ba[l] = (const float*)d_in[base + 6];
            bb[l] = (const float*)d_in[base + 7];
            m[l]  = (const int*)  d_in[base + 8];
        }
        x  = (const float*)d_in[27];
        dt = (const float*)d_in[28];
    }

    cfc_precompute_kernel<<<148, 256>>>(
        w1[0], w2[0], wa[0], wb[0], ba[0], bb[0], m[0],
        w1[1], w2[1], wa[1], wb[1], ba[1], bb[1], m[1],
        w1[2], w2[2], wa[2], wb[2], ba[2], bb[2], m[2],
        dt);

    cudaFuncSetAttribute(cfc_main_kernel,
                         cudaFuncAttributeMaxDynamicSharedMemorySize, SMEM_BYTES);

    int write_h = (out_size >= BB * TT * NM + BB * 256) ? 1 : 0;
    cfc_main_kernel<<<(BB / ROWS) * 2, NTH, SMEM_BYTES>>>(
        x, b1[0], b2[0], b1[1], b2[1], b1[2], b2[2],
        (float*)d_out, write_h);
}

// round 15
// speedup vs baseline: 1.5203x; 1.0396x over previous
#include <cuda_runtime.h>
#include <cuda_fp16.h>
#include <math.h>

typedef unsigned long long ull;

// Problem constants
#define BB   256
#define TT   512
#define IND  128
#define NI   149
#define NCC  99
#define NM   8
#define CAT0 277
#define CAT1 248
#define CAT2 107
#define K0P  280          // 5 chunks x 56
#define K1P  252          // 4 chunks x 63
#define ROWS 4
#define NTH  480
#define RS0  240          // gmem fused row stride layer0 (3*76=228 active), halfs
#define RS1  160          // gmem fused row stride layer1 (3*52=156 active), halfs
#define SS0  228          // smem compact row stride layer0, halfs (456B, 8B-mult)

// SMEM layout (float offsets)
#define XB0F  2240        // 280*8
#define XB1F  2016        // 252*8
#define XB2F  448         // 112*4
#define OFF_XH0   0
#define OFF_XH1   4480
#define OFF_XH2   8512
#define OFF_PARTA 9408    // 5*3*4*80 = 4800
#define OFF_PARTB 14208   // 4*3*4*56 = 2688
#define OFF_SW2   16896   // 3*107*8 = 2568
#define OFF_MBAR  19464   // 8 mbarriers = 16 floats
#define OFF_SW0   19480   // 280*228 halfs = 31920 floats (127.7KB)
#define SMEM_FLOATS (19480 + 31920)
#define SMEM_BYTES  (SMEM_FLOATS * 4)   // 205,600 B

#define MB_RDYA(s)  (OFF_MBAR + 0 + 2*(s))
#define MB_CONB(s)  (OFF_MBAR + 4 + 2*(s))
#define MB_RDYB(s)  (OFF_MBAR + 8 + 2*(s))
#define MB_CONC(s)  (OFF_MBAR + 12 + 2*(s))

// Fused per-rank weight arrays, fp16 storage (fp32 accumulate in kernel).
__device__ __half g_W0h[2][K0P * RS0];
__device__ __half g_W1h[2][K1P * RS1];
__device__ float  g_W2[3][CAT2 * 8];
__device__ float  g_bc[NI + NCC + NM];

// ---------------------------------------------------------------------------
__global__ void cfc_precompute_kernel(
    const float* __restrict__ w1_0, const float* __restrict__ w2_0,
    const float* __restrict__ wa_0, const float* __restrict__ wb_0,
    const float* __restrict__ ba_0, const float* __restrict__ bb_0,
    const int*   __restrict__ m0,
    const float* __restrict__ w1_1, const float* __restrict__ w2_1,
    const float* __restrict__ wa_1, const float* __restrict__ wb_1,
    const float* __restrict__ ba_1, const float* __restrict__ bb_1,
    const int*   __restrict__ m1,
    const float* __restrict__ w1_2, const float* __restrict__ w2_2,
    const float* __restrict__ wa_2, const float* __restrict__ wb_2,
    const float* __restrict__ ba_2, const float* __restrict__ bb_2,
    const int*   __restrict__ m2,
    const float* __restrict__ dt)
{
    const float ts = dt[0];
    const int idx    = blockIdx.x * blockDim.x + threadIdx.x;
    const int stride = gridDim.x * blockDim.x;

    // layer-0 fused: rank r, row k, col c: c<228 -> mat=c/76, jl=c%76
    for (int i = idx; i < 2 * K0P * RS0; i += stride) {
        int r = i / (K0P * RS0), rem = i - r * (K0P * RS0);
        int k = rem / RS0, c = rem - k * RS0;
        float v = 0.f;
        if (c < 228 && k < CAT0) {
            int mat = c / 76, jl = c - mat * 76;
            int jb = r ? 76 : 0, nj = r ? 73 : 76;
            if (jl < nj) {
                int j = jb + jl;
                int src = j * CAT0 + k;
                float mm = (float)m0[src];
                if (mat == 0)      v = w1_0[src] * mm;
                else if (mat == 1) v = w2_0[src] * mm;
                else               v = ts * wa_0[src] + wb_0[src];
            }
        }
        g_W0h[r][k * RS0 + c] = __float2half(v);
    }
    // layer-1 fused: c<156 -> mat=c/52, jl=c%52
    for (int i = idx; i < 2 * K1P * RS1; i += stride) {
        int r = i / (K1P * RS1), rem = i - r * (K1P * RS1);
        int k = rem / RS1, c = rem - k * RS1;
        float v = 0.f;
        if (c < 156 && k < CAT1) {
            int mat = c / 52, jl = c - mat * 52;
            int jb = r ? 52 : 0, nj = r ? 47 : 52;
            if (jl < nj) {
                int j = jb + jl;
                int src = j * CAT1 + k;
                float mm = (float)m1[src];
                if (mat == 0)      v = w1_1[src] * mm;
                else if (mat == 1) v = w2_1[src] * mm;
                else               v = ts * wa_1[src] + wb_1[src];
            }
        }
        g_W1h[r][k * RS1 + c] = __float2half(v);
    }
    for (int i = idx; i < CAT2 * 8; i += stride) {
        int k = i / 8, j = i - k * 8;
        int src = j * CAT2 + k;
        float mm = (float)m2[src];
        g_W2[0][i] = w1_2[src] * mm;
        g_W2[1][i] = w2_2[src] * mm;
        g_W2[2][i] = ts * wa_2[src] + wb_2[src];
    }
    for (int j = idx; j < NI;  j += stride) g_bc[j]            = ts * ba_0[j] + bb_0[j];
    for (int j = idx; j < NCC; j += stride) g_bc[NI + j]       = ts * ba_1[j] + bb_1[j];
    for (int j = idx; j < NM;  j += stride) g_bc[NI + NCC + j] = ts * ba_2[j] + bb_2[j];
}

// ---------------------------------------------------------------------------
__device__ __forceinline__ ull pack2(float a, float b) {
    ull r; asm("mov.b64 %0, {%1, %2};" : "=l"(r) : "f"(a), "f"(b)); return r;
}
__device__ __forceinline__ void unpack2(ull v, float& a, float& b) {
    asm("mov.b64 {%0, %1}, %2;" : "=f"(a), "=f"(b) : "l"(v));
}
__device__ __forceinline__ ull fma2(ull a, ull b, ull c) {
    ull d; asm("fma.rn.f32x2 %0, %1, %2, %3;" : "=l"(d) : "l"(a), "l"(b), "l"(c)); return d;
}
// Load 4 fp16 weights (8B) from GMEM and expand to two f32x2 pairs
__device__ __forceinline__ void ldw4_h(const __half* p, ull& wx, ull& wy) {
    unsigned lo, hi;
    asm("ld.global.nc.v2.u32 {%0, %1}, [%2];" : "=r"(lo), "=r"(hi) : "l"(p));
    float2 f01 = __half22float2(*(__half2*)&lo);
    float2 f23 = __half22float2(*(__half2*)&hi);
    wx = pack2(f01.x, f01.y);
    wy = pack2(f23.x, f23.y);
}
// Same but from SMEM (compiler emits LDS.64)
__device__ __forceinline__ void ldw4_hs(const __half* p, ull& wx, ull& wy) {
    uint2 v = *(const uint2*)p;
    float2 f01 = __half22float2(*(__half2*)&v.x);
    float2 f23 = __half22float2(*(__half2*)&v.y);
    wx = pack2(f01.x, f01.y);
    wy = pack2(f23.x, f23.y);
}
__device__ __forceinline__ float sigmoidf_(float z) { return 1.0f / (1.0f + expf(-z)); }
__device__ __forceinline__ float cfc_mix(float a1, float a2, float ac,
                                         float b1, float b2, float bc) {
    float ff1 = tanhf(a1 + b1);
    float ff2 = tanhf(a2 + b2);
    float ti  = sigmoidf_(ac + bc);
    return ff1 + ti * (ff2 - ff1);
}
__device__ __forceinline__ unsigned smem_u32(const void* p) {
    unsigned a;
    asm("{ .reg .u64 t; cvta.to.shared.u64 t, %1; cvt.u32.u64 %0, t; }" : "=r"(a) : "l"(p));
    return a;
}
__device__ __forceinline__ void mbar_init(unsigned addr, unsigned count) {
    asm volatile("mbarrier.init.shared.b64 [%0], %1;" :: "r"(addr), "r"(count) : "memory");
}
__device__ __forceinline__ void mbar_wait(unsigned addr, unsigned parity) {
    unsigned done = 0;
    do {
        asm volatile(
            "{\n\t.reg .pred P;\n\t"
            "mbarrier.try_wait.parity.acquire.cluster.shared::cta.b64 P, [%1], %2, 0x989680;\n\t"
            "selp.b32 %0, 1, 0, P;\n\t}"
            : "=r"(done) : "r"(addr), "r"(parity) : "memory");
    } while (!done);
}
__device__ __forceinline__ void mbar_arrive_local(unsigned addr) {
    asm volatile("mbarrier.arrive.release.cluster.shared::cta.b64 _, [%0];"
                 :: "r"(addr) : "memory");
}
__device__ __forceinline__ void mbar_arrive_peer(unsigned addr, unsigned peer) {
    asm volatile(
        "{\n\t.reg .b32 ra;\n\t"
        "mapa.shared::cluster.u32 ra, %0, %1;\n\t"
        "mbarrier.arrive.release.cluster.shared::cluster.b64 _, [ra];\n\t}"
        :: "r"(addr), "r"(peer) : "memory");
}
__device__ __forceinline__ void cfence() {
    asm volatile("fence.acq_rel.cluster;" ::: "memory");
}
__device__ __forceinline__ void st_peer_u64(unsigned addr, unsigned peer, ull v) {
    asm volatile(
        "{\n\t.reg .b32 ra;\n\t"
        "mapa.shared::cluster.u32 ra, %0, %1;\n\t"
        "st.shared::cluster.u64 [ra], %2;\n\t}"
        :: "r"(addr), "r"(peer), "l"(v) : "memory");
}
__device__ __forceinline__ void st_peer_u32(unsigned addr, unsigned peer, float v) {
    asm volatile(
        "{\n\t.reg .b32 ra;\n\t"
        "mapa.shared::cluster.u32 ra, %0, %1;\n\t"
        "st.shared::cluster.f32 [ra], %2;\n\t}"
        :: "r"(addr), "r"(peer), "f"(v) : "memory");
}
#define BARN(id, n) asm volatile("bar.sync %0, %1;" :: "r"(id), "r"(n) : "memory")

// ---------------------------------------------------------------------------
// Pipelined kernel (R14 structure): 64 clusters x 2 CTAs, 4 rows/cluster,
// j split across pair; warps 0-8 = layer0 (A, SMEM-resident fp16 weights),
// 9-13 = layer1 (B, LDG fp16 weights), warp 14 = layer2 (C).
// ---------------------------------------------------------------------------
__global__ __launch_bounds__(NTH, 1) __cluster_dims__(2, 1, 1)
void cfc_main_kernel(
    const float* __restrict__ x,
    const float* __restrict__ b1_0, const float* __restrict__ b2_0,
    const float* __restrict__ b1_1, const float* __restrict__ b2_1,
    const float* __restrict__ b1_2, const float* __restrict__ b2_2,
    float* __restrict__ out, int write_h)
{
    extern __shared__ float sm[];
    float* xh0A  = sm + OFF_XH0;
    float* xh1A  = sm + OFF_XH1;
    float* xh2A  = sm + OFF_XH2;
    float* partA = sm + OFF_PARTA;
    float* partB = sm + OFF_PARTB;
    float* sw2   = sm + OFF_SW2;
    __half* sw0h = (__half*)(sm + OFF_SW0);

    const int tid = threadIdx.x;
    unsigned rank;
    asm("mov.u32 %0, %%cluster_ctarank;" : "=r"(rank));
    const unsigned peer = rank ^ 1u;
    const int b0 = (blockIdx.x >> 1) * ROWS;

    const int nj0 = rank ? 73 : 76;
    const int jb0 = rank ? 76 : 0;
    const int nj1 = rank ? 47 : 52;
    const int jb1 = rank ? 52 : 0;

    const unsigned sbase = smem_u32(sm);

    const bool isA = (tid < 288);
    const bool isB = (tid >= 288 && tid < 448);

    // stage A: 57 combos (mat*19+jg) x 5 kc(56)
    const int at = tid;
    const int comboA = at % 57, kcA = at / 57;
    const int matA = comboA / 19, jgA = comboA % 19;
    const bool actA = isA && (at < 285);
    const bool combA = isA && (at < 152);
    const int cjA = at >> 1, crA = (at & 1) * 2;

    // stage B: 39 combos (mat*13+jg) x 4 kc(63)
    const int bt = tid - 288;
    const int comboB = bt % 39, kcB = bt / 39;
    const int matB = comboB / 13, jgB = comboB % 13;
    const bool actB = isB && (bt < 156);
    const bool combB = isB && (bt < 104);
    const int cjB = bt >> 1, crB = (bt & 1) * 2;

    // stage C
    const int ct = tid - 448;
    const int matC = ct >> 3, jC = ct & 7;
    const bool actC = (tid >= 448) && (ct < 24);

    // ---- prologue ----
    for (int i = tid; i < 2 * XB0F; i += NTH) xh0A[i] = 0.f;
    for (int i = tid; i < 2 * XB1F; i += NTH) xh1A[i] = 0.f;
    for (int i = tid; i < 2 * XB2F; i += NTH) xh2A[i] = 0.f;
    for (int i = tid; i < 3 * CAT2 * 8; i += NTH) sw2[i] = ((const float*)g_W2)[i];
    // copy this rank's layer-0 fp16 slice into SMEM (compact stride 228 halfs)
    {
        const unsigned* gw0 = (const unsigned*)g_W0h[rank];
        unsigned* sw0u = (unsigned*)sw0h;
        for (int i = tid; i < K0P * (SS0 / 2); i += NTH) {
            int k = i / (SS0 / 2), c = i - k * (SS0 / 2);
            sw0u[i] = gw0[k * (RS0 / 2) + c];
        }
    }
    if (tid == 0) {
        for (int s = 0; s < 2; ++s) {
            mbar_init(sbase + MB_RDYA(s) * 4, 2);
            mbar_init(sbase + MB_CONB(s) * 4, 2);
            mbar_init(sbase + MB_RDYB(s) * 4, 2);
            mbar_init(sbase + MB_CONC(s) * 4, 2);
        }
    }

    float bA1 = 0.f, bA2 = 0.f, bAc = 0.f;
    if (combA && cjA < nj0) { bA1 = b1_0[jb0 + cjA]; bA2 = b2_0[jb0 + cjA]; bAc = g_bc[jb0 + cjA]; }
    float bB1 = 0.f, bB2 = 0.f, bBc = 0.f;
    if (combB && cjB < nj1) { bB1 = b1_1[jb1 + cjB]; bB2 = b2_1[jb1 + cjB]; bBc = g_bc[NI + jb1 + cjB]; }
    float bC1 = 0.f, bC2 = 0.f, bCc = 0.f;
    if (tid >= 448) { bC1 = b1_2[jC]; bC2 = b2_2[jC]; bCc = g_bc[NI + NCC + jC]; }

    for (int i = tid; i < ROWS * IND; i += NTH) {
        int r = i >> 7, k = i & 127;
        float v = x[((size_t)(b0 + r) * TT + 0) * IND + k];
        *(ull*)&xh0A[k * 8 + r * 2] = pack2(v, v);
    }
    float xr0 = 0.f, xr1 = 0.f;
    const int i0 = tid, i1 = tid + 288;
    if (isA) {
        xr0 = x[((size_t)(b0 + (i0 >> 7)) * TT + 1) * IND + (i0 & 127)];
        if (i1 < ROWS * IND)
            xr1 = x[((size_t)(b0 + (i1 >> 7)) * TT + 1) * IND + (i1 & 127)];
    }

    __syncthreads();
    asm volatile("barrier.cluster.arrive.aligned;" ::: "memory");
    asm volatile("barrier.cluster.wait.aligned;" ::: "memory");

    if (isA) {
        // =================== STAGE A : layer 0 (SMEM weights) ===================
        const __half* WbA = sw0h + (size_t)(kcA * 56) * SS0 + comboA * 4;
        for (int t = 0; t < TT; ++t) {
            const int pr = t & 1, pw = (t + 1) & 1;
            float* xh0r = xh0A + pr * XB0F;
            float* xh0w = xh0A + pw * XB0F;
            float* xh1c = xh1A + pr * XB1F;

            if (t >= 1)
                mbar_wait(sbase + MB_RDYA((t - 1) & 1) * 4, ((t - 1) >> 1) & 1);

            if (actA) {
                const __half* Wp = WbA;
                const float* ab = xh0r + (kcA * 56) * 8;
                ull aA0 = 0, aB0 = 0, aA1 = 0, aB1 = 0;
                ull aA2 = 0, aB2 = 0, aA3 = 0, aB3 = 0;
                #pragma unroll 8
                for (int k = 0; k < 56; ++k) {
                    ull wx, wy;
                    ldw4_hs(Wp + (size_t)k * SS0, wx, wy);
                    ulonglong2 d01 = *(const ulonglong2*)(ab + k * 8);
                    ulonglong2 d23 = *(const ulonglong2*)(ab + k * 8 + 4);
                    aA0 = fma2(wx, d01.x, aA0); aB0 = fma2(wy, d01.x, aB0);
                    aA1 = fma2(wx, d01.y, aA1); aB1 = fma2(wy, d01.y, aB1);
                    aA2 = fma2(wx, d23.x, aA2); aB2 = fma2(wy, d23.x, aB2);
                    aA3 = fma2(wx, d23.y, aA3); aB3 = fma2(wy, d23.y, aB3);
                }
                float* P = partA + (size_t)((kcA * 3 + matA) * 4) * 80 + jgA * 4;
                *(ulonglong2*)(P)       = make_ulonglong2(aA0, aB0);
                *(ulonglong2*)(P + 80)  = make_ulonglong2(aA1, aB1);
                *(ulonglong2*)(P + 160) = make_ulonglong2(aA2, aB2);
                *(ulonglong2*)(P + 240) = make_ulonglong2(aA3, aB3);
            }
            BARN(1, 288);

            if (t >= 2)
                mbar_wait(sbase + MB_CONB(t & 1) * 4, ((t - 2) >> 1) & 1);

            if (combA && cjA < nj0) {
                const int r0 = crA, r1 = crA + 1;
                float a1r0 = 0, a1r1 = 0, a2r0 = 0, a2r1 = 0, acr0 = 0, acr1 = 0;
                #pragma unroll
                for (int c = 0; c < 5; ++c) {
                    const float* P = partA + (size_t)(c * 12) * 80;
                    a1r0 += P[(0 * 4 + r0) * 80 + cjA];
                    a1r1 += P[(0 * 4 + r1) * 80 + cjA];
                    a2r0 += P[(1 * 4 + r0) * 80 + cjA];
                    a2r1 += P[(1 * 4 + r1) * 80 + cjA];
                    acr0 += P[(2 * 4 + r0) * 80 + cjA];
                    acr1 += P[(2 * 4 + r1) * 80 + cjA];
                }
                float h0v = cfc_mix(a1r0, a2r0, acr0, bA1, bA2, bAc);
                float h1v = cfc_mix(a1r1, a2r1, acr1, bA1, bA2, bAc);
                ull u0 = pack2(h0v, h0v), u1 = pack2(h1v, h1v);
                const int jg = jb0 + cjA;
                const int oX = (IND + jg) * 8;
                const int oH = jg * 8;
                *(ull*)&xh0w[oX + r0 * 2] = u0;
                *(ull*)&xh0w[oX + r1 * 2] = u1;
                *(ull*)&xh1c[oH + r0 * 2] = u0;
                *(ull*)&xh1c[oH + r1 * 2] = u1;
                st_peer_u64(sbase + (OFF_XH0 + pw * XB0F + oX + r0 * 2) * 4, peer, u0);
                st_peer_u64(sbase + (OFF_XH0 + pw * XB0F + oX + r1 * 2) * 4, peer, u1);
                st_peer_u64(sbase + (OFF_XH1 + pr * XB1F + oH + r0 * 2) * 4, peer, u0);
                st_peer_u64(sbase + (OFF_XH1 + pr * XB1F + oH + r1 * 2) * 4, peer, u1);
            }
            *(ull*)&xh0w[(i0 & 127) * 8 + (i0 >> 7) * 2] = pack2(xr0, xr0);
            if (i1 < ROWS * IND)
                *(ull*)&xh0w[(i1 & 127) * 8 + (i1 >> 7) * 2] = pack2(xr1, xr1);
            {
                int tn = t + 2; if (tn > TT - 1) tn = TT - 1;
                xr0 = x[((size_t)(b0 + (i0 >> 7)) * TT + tn) * IND + (i0 & 127)];
                if (i1 < ROWS * IND)
                    xr1 = x[((size_t)(b0 + (i1 >> 7)) * TT + tn) * IND + (i1 & 127)];
            }
            BARN(1, 288);
            if (tid == 0) {
                cfence();
                mbar_arrive_local(sbase + MB_RDYA(t & 1) * 4);
                mbar_arrive_peer(sbase + MB_RDYA(t & 1) * 4, peer);
            }
        }
    } else if (isB) {
        // =================== STAGE B : layer 1 (LDG weights) ===================
        const __half* WbB = g_W1h[rank] + (size_t)(kcB * 63) * RS1 + comboB * 4;
        for (int t = 0; t < TT; ++t) {
            const int pr = t & 1, pw = (t + 1) & 1;
            float* xh1r = xh1A + pr * XB1F;
            float* xh1w = xh1A + pw * XB1F;
            float* xh2c = xh2A + pr * XB2F;

            mbar_wait(sbase + MB_RDYA(t & 1) * 4, (t >> 1) & 1);
            if (t >= 1)
                mbar_wait(sbase + MB_RDYB((t - 1) & 1) * 4, ((t - 1) >> 1) & 1);

            if (actB) {
                const __half* Wp = WbB;
                const float* ab = xh1r + (kcB * 63) * 8;
                ull aA0 = 0, aB0 = 0, aA1 = 0, aB1 = 0;
                ull aA2 = 0, aB2 = 0, aA3 = 0, aB3 = 0;
                #pragma unroll 7
                for (int k = 0; k < 63; ++k) {
                    ull wx, wy;
                    ldw4_h(Wp + (size_t)k * RS1, wx, wy);
                    ulonglong2 d01 = *(const ulonglong2*)(ab + k * 8);
                    ulonglong2 d23 = *(const ulonglong2*)(ab + k * 8 + 4);
                    aA0 = fma2(wx, d01.x, aA0); aB0 = fma2(wy, d01.x, aB0);
                    aA1 = fma2(wx, d01.y, aA1); aB1 = fma2(wy, d01.y, aB1);
                    aA2 = fma2(wx, d23.x, aA2); aB2 = fma2(wy, d23.x, aB2);
                    aA3 = fma2(wx, d23.y, aA3); aB3 = fma2(wy, d23.y, aB3);
                }
                float* P = partB + (size_t)((kcB * 3 + matB) * 4) * 56 + jgB * 4;
                *(ulonglong2*)(P)       = make_ulonglong2(aA0, aB0);
                *(ulonglong2*)(P + 56)  = make_ulonglong2(aA1, aB1);
                *(ulonglong2*)(P + 112) = make_ulonglong2(aA2, aB2);
                *(ulonglong2*)(P + 168) = make_ulonglong2(aA3, aB3);
            }
            BARN(2, 160);
            if (bt == 0) {
                mbar_arrive_local(sbase + MB_CONB(t & 1) * 4);
                mbar_arrive_peer(sbase + MB_CONB(t & 1) * 4, peer);
            }
            if (t >= 2)
                mbar_wait(sbase + MB_CONC(t & 1) * 4, ((t - 2) >> 1) & 1);

            if (combB && cjB < nj1) {
                const int r0 = crB, r1 = crB + 1;
                float a1r0 = 0, a1r1 = 0, a2r0 = 0, a2r1 = 0, acr0 = 0, acr1 = 0;
                #pragma unroll
                for (int c = 0; c < 4; ++c) {
                    const float* P = partB + (size_t)(c * 12) * 56;
                    a1r0 += P[(0 * 4 + r0) * 56 + cjB];
                    a1r1 += P[(0 * 4 + r1) * 56 + cjB];
                    a2r0 += P[(1 * 4 + r0) * 56 + cjB];
                    a2r1 += P[(1 * 4 + r1) * 56 + cjB];
                    acr0 += P[(2 * 4 + r0) * 56 + cjB];
                    acr1 += P[(2 * 4 + r1) * 56 + cjB];
                }
                float h0v = cfc_mix(a1r0, a2r0, acr0, bB1, bB2, bBc);
                float h1v = cfc_mix(a1r1, a2r1, acr1, bB1, bB2, bBc);
                ull u0 = pack2(h0v, h0v), u1 = pack2(h1v, h1v);
                const int jg = jb1 + cjB;
                const int oH = (NI + jg) * 8;
                const int o2 = jg * 4;
                *(ull*)&xh1w[oH + r0 * 2] = u0;
                *(ull*)&xh1w[oH + r1 * 2] = u1;
                xh2c[o2 + r0] = h0v;
                xh2c[o2 + r1] = h1v;
                st_peer_u64(sbase + (OFF_XH1 + pw * XB1F + oH + r0 * 2) * 4, peer, u0);
                st_peer_u64(sbase + (OFF_XH1 + pw * XB1F + oH + r1 * 2) * 4, peer, u1);
                st_peer_u32(sbase + (OFF_XH2 + pr * XB2F + o2 + r0) * 4, peer, h0v);
                st_peer_u32(sbase + (OFF_XH2 + pr * XB2F + o2 + r1) * 4, peer, h1v);
            }
            BARN(2, 160);
            if (bt == 0) {
                cfence();
                mbar_arrive_local(sbase + MB_RDYB(t & 1) * 4);
                mbar_arrive_peer(sbase + MB_RDYB(t & 1) * 4, peer);
            }
        }
    } else {
        // =================== STAGE C : layer 2 ===================
        for (int t = 0; t < TT; ++t) {
            const int pr = t & 1, pw = (t + 1) & 1;
            float* xh2r = xh2A + pr * XB2F;
            float* xh2w = xh2A + pw * XB2F;

            mbar_wait(sbase + MB_RDYB(t & 1) * 4, (t >> 1) & 1);

            ull acc01 = 0, acc23 = 0;
            if (actC) {
                const float* W = sw2 + matC * (CAT2 * 8) + jC;
                #pragma unroll 4
                for (int k = 0; k < CAT2; ++k) {
                    float w = W[k * 8];
                    ull ww = pack2(w, w);
                    ulonglong2 u = *(const ulonglong2*)(xh2r + k * 4);
                    acc01 = fma2(ww, u.x, acc01);
                    acc23 = fma2(ww, u.y, acc23);
                }
            }
            __syncwarp();
            if (ct == 0) {
                mbar_arrive_local(sbase + MB_CONC(t & 1) * 4);
                mbar_arrive_peer(sbase + MB_CONC(t & 1) * 4, peer);
            }
            ull m1_01 = __shfl_sync(0xffffffffu, acc01, 8 + jC);
            ull m1_23 = __shfl_sync(0xffffffffu, acc23, 8 + jC);
            ull m2_01 = __shfl_sync(0xffffffffu, acc01, 16 + jC);
            ull m2_23 = __shfl_sync(0xffffffffu, acc23, 16 + jC);
            if (ct < 8) {
                float a1[4], a2[4], ac[4];
                unpack2(acc01, a1[0], a1[1]); unpack2(acc23, a1[2], a1[3]);
                unpack2(m1_01, a2[0], a2[1]); unpack2(m1_23, a2[2], a2[3]);
                unpack2(m2_01, ac[0], ac[1]); unpack2(m2_23, ac[2], ac[3]);
                #pragma unroll
                for (int r = 0; r < 4; ++r) {
                    float h = cfc_mix(a1[r], a2[r], ac[r], bC1, bC2, bCc);
                    xh2w[(NCC + jC) * 4 + r] = h;
                    if (rank == 0)
                        out[((size_t)(b0 + r) * TT + t) * NM + jC] = tanhf(h);
                }
            }
            __syncwarp();
        }
    }

    __syncthreads();
    asm volatile("barrier.cluster.arrive.aligned;" ::: "memory");
    asm volatile("barrier.cluster.wait.aligned;" ::: "memory");
    cfence();

    if (write_h && rank == 0) {
        size_t base = (size_t)BB * TT * NM;
        for (int jt = tid; jt < 256; jt += NTH) {
            #pragma unroll
            for (int r = 0; r < 4; ++r) {
                float v;
                if (jt < NI)            v = xh0A[(IND + jt) * 8 + r * 2];
                else if (jt < NI + NCC) v = xh1A[(NI + (jt - NI)) * 8 + r * 2];
                else                    v = xh2A[(NCC + (jt - NI - NCC)) * 4 + r];
                out[base + (size_t)(b0 + r) * 256 + jt] = v;
            }
        }
    }
    asm volatile("barrier.cluster.arrive.aligned;" ::: "memory");
    asm volatile("barrier.cluster.wait.aligned;" ::: "memory");
}

// ---------------------------------------------------------------------------
extern "C" void kernel_launch(void* const* d_in, const int* in_sizes, int n_in,
                              void* d_out, int out_size)
{
    const float *x, *dt;
    const float *w1[3], *b1[3], *w2[3], *b2[3], *wa[3], *ba[3], *wb[3], *bb[3];
    const int   *m[3];

    if (in_sizes[0] == BB * TT * IND) {
        x  = (const float*)d_in[0];
        dt = (const float*)d_in[1];
        for (int l = 0; l < 3; l++) {
            int base = 2 + 9 * l;
            w1[l] = (const float*)d_in[base + 0];
            b1[l] = (const float*)d_in[base + 1];
            w2[l] = (const float*)d_in[base + 2];
            b2[l] = (const float*)d_in[base + 3];
            wa[l] = (const float*)d_in[base + 4];
            ba[l] = (const float*)d_in[base + 5];
            wb[l] = (const float*)d_in[base + 6];
            bb[l] = (const float*)d_in[base + 7];
            m[l]  = (const int*)  d_in[base + 8];
        }
    } else {
        for (int l = 0; l < 3; l++) {
            int base = 9 * l;
            w1[l] = (const float*)d_in[base + 0];
            w2[l] = (const float*)d_in[base + 1];
            wa[l] = (const float*)d_in[base + 2];
            wb[l] = (const float*)d_in[base + 3];
            b1[l] = (const float*)d_in[base + 4];
            b2[l] = (const float*)d_in[base + 5];
            ba[l] = (const float*)d_in[base + 6];
            bb[l] = (const float*)d_in[base + 7];
            m[l]  = (const int*)  d_in[base + 8];
        }
        x  = (const float*)d_in[27];
        dt = (const float*)d_in[28];
    }

    cfc_precompute_kernel<<<148, 256>>>(
        w1[0], w2[0], wa[0], wb[0], ba[0], bb[0], m[0],
        w1[1], w2[1], wa[1], wb[1], ba[1], bb[1], m[1],
        w1[2], w2[2], wa[2], wb[2], ba[2], bb[2], m[2],
        dt);

    cudaFuncSetAttribute(cfc_main_kernel,
                         cudaFuncAttributeMaxDynamicSharedMemorySize, SMEM_BYTES);

    int write_h = (out_size >= BB * TT * NM + BB * 256) ? 1 : 0;
    cfc_main_kernel<<<(BB / ROWS) * 2, NTH, SMEM_BYTES>>>(
        x, b1[0], b2[0], b1[1], b2[1], b1[2], b2[2],
        (float*)d_out, write_h);
}

// round 16
// speedup vs baseline: 1.7203x; 1.1315x over previous
#include <cuda_runtime.h>
#include <cuda_fp16.h>
#include <math.h>

typedef unsigned long long ull;

// Problem constants
#define BB   256
#define TT   512
#define IND  128
#define NI   149
#define NCC  99
#define NM   8
#define CAT0 277
#define CAT1 248
#define CAT2 107
#define K0P  280          // 5 chunks x 56
#define K1P  252          // 4 chunks x 63
#define ROWS 4
#define NTH  480
#define RS0  240          // gmem fused row stride layer0 (3*76=228 active), halfs
#define RS1  160          // gmem fused row stride layer1 (3*52=156 active), halfs
#define SS1  156          // smem compact row stride layer1, halfs (312B, 8B-mult)

// SMEM layout (float offsets)
#define XB0F  2240        // 280*8
#define XB1F  2016        // 252*8
#define XB2F  448         // 112*4
#define OFF_XH0   0
#define OFF_XH1   4480
#define OFF_XH2   8512
#define OFF_PARTA 9408    // 5*3*4*80 = 4800
#define OFF_PARTB 14208   // 4*3*4*56 = 2688
#define OFF_SW2   16896   // 3*107*8 = 2568
#define OFF_MBAR  19464   // 8 mbarriers = 16 floats
#define OFF_SW1   19480   // 252*156 halfs = 19656 floats (78.6KB)
#define SMEM_FLOATS (19480 + 19656)
#define SMEM_BYTES  (SMEM_FLOATS * 4)   // 156,544 B

#define MB_RDYA(s)  (OFF_MBAR + 0 + 2*(s))
#define MB_CONB(s)  (OFF_MBAR + 4 + 2*(s))
#define MB_RDYB(s)  (OFF_MBAR + 8 + 2*(s))
#define MB_CONC(s)  (OFF_MBAR + 12 + 2*(s))

// Fused per-rank weight arrays, fp16 storage (fp32 accumulate in kernel).
__device__ __half g_W0h[2][K0P * RS0];
__device__ __half g_W1h[2][K1P * RS1];
__device__ float  g_W2[3][CAT2 * 8];
__device__ float  g_bc[NI + NCC + NM];

// ---------------------------------------------------------------------------
__global__ void cfc_precompute_kernel(
    const float* __restrict__ w1_0, const float* __restrict__ w2_0,
    const float* __restrict__ wa_0, const float* __restrict__ wb_0,
    const float* __restrict__ ba_0, const float* __restrict__ bb_0,
    const int*   __restrict__ m0,
    const float* __restrict__ w1_1, const float* __restrict__ w2_1,
    const float* __restrict__ wa_1, const float* __restrict__ wb_1,
    const float* __restrict__ ba_1, const float* __restrict__ bb_1,
    const int*   __restrict__ m1,
    const float* __restrict__ w1_2, const float* __restrict__ w2_2,
    const float* __restrict__ wa_2, const float* __restrict__ wb_2,
    const float* __restrict__ ba_2, const float* __restrict__ bb_2,
    const int*   __restrict__ m2,
    const float* __restrict__ dt)
{
    const float ts = dt[0];
    const int idx    = blockIdx.x * blockDim.x + threadIdx.x;
    const int stride = gridDim.x * blockDim.x;

    // layer-0 fused: rank r, row k, col c: c<228 -> mat=c/76, jl=c%76
    for (int i = idx; i < 2 * K0P * RS0; i += stride) {
        int r = i / (K0P * RS0), rem = i - r * (K0P * RS0);
        int k = rem / RS0, c = rem - k * RS0;
        float v = 0.f;
        if (c < 228 && k < CAT0) {
            int mat = c / 76, jl = c - mat * 76;
            int jb = r ? 76 : 0, nj = r ? 73 : 76;
            if (jl < nj) {
                int j = jb + jl;
                int src = j * CAT0 + k;
                float mm = (float)m0[src];
                if (mat == 0)      v = w1_0[src] * mm;
                else if (mat == 1) v = w2_0[src] * mm;
                else               v = ts * wa_0[src] + wb_0[src];
            }
        }
        g_W0h[r][k * RS0 + c] = __float2half(v);
    }
    // layer-1 fused: c<156 -> mat=c/52, jl=c%52
    for (int i = idx; i < 2 * K1P * RS1; i += stride) {
        int r = i / (K1P * RS1), rem = i - r * (K1P * RS1);
        int k = rem / RS1, c = rem - k * RS1;
        float v = 0.f;
        if (c < 156 && k < CAT1) {
            int mat = c / 52, jl = c - mat * 52;
            int jb = r ? 52 : 0, nj = r ? 47 : 52;
            if (jl < nj) {
                int j = jb + jl;
                int src = j * CAT1 + k;
                float mm = (float)m1[src];
                if (mat == 0)      v = w1_1[src] * mm;
                else if (mat == 1) v = w2_1[src] * mm;
                else               v = ts * wa_1[src] + wb_1[src];
            }
        }
        g_W1h[r][k * RS1 + c] = __float2half(v);
    }
    for (int i = idx; i < CAT2 * 8; i += stride) {
        int k = i / 8, j = i - k * 8;
        int src = j * CAT2 + k;
        float mm = (float)m2[src];
        g_W2[0][i] = w1_2[src] * mm;
        g_W2[1][i] = w2_2[src] * mm;
        g_W2[2][i] = ts * wa_2[src] + wb_2[src];
    }
    for (int j = idx; j < NI;  j += stride) g_bc[j]            = ts * ba_0[j] + bb_0[j];
    for (int j = idx; j < NCC; j += stride) g_bc[NI + j]       = ts * ba_1[j] + bb_1[j];
    for (int j = idx; j < NM;  j += stride) g_bc[NI + NCC + j] = ts * ba_2[j] + bb_2[j];
}

// ---------------------------------------------------------------------------
__device__ __forceinline__ ull pack2(float a, float b) {
    ull r; asm("mov.b64 %0, {%1, %2};" : "=l"(r) : "f"(a), "f"(b)); return r;
}
__device__ __forceinline__ void unpack2(ull v, float& a, float& b) {
    asm("mov.b64 {%0, %1}, %2;" : "=f"(a), "=f"(b) : "l"(v));
}
__device__ __forceinline__ ull fma2(ull a, ull b, ull c) {
    ull d; asm("fma.rn.f32x2 %0, %1, %2, %3;" : "=l"(d) : "l"(a), "l"(b), "l"(c)); return d;
}
// Load 4 fp16 weights (8B) from GMEM and expand to two f32x2 pairs
__device__ __forceinline__ void ldw4_h(const __half* p, ull& wx, ull& wy) {
    unsigned lo, hi;
    asm("ld.global.nc.v2.u32 {%0, %1}, [%2];" : "=r"(lo), "=r"(hi) : "l"(p));
    float2 f01 = __half22float2(*(__half2*)&lo);
    float2 f23 = __half22float2(*(__half2*)&hi);
    wx = pack2(f01.x, f01.y);
    wy = pack2(f23.x, f23.y);
}
// Same but from SMEM (LDS.64)
__device__ __forceinline__ void ldw4_hs(const __half* p, ull& wx, ull& wy) {
    uint2 v = *(const uint2*)p;
    float2 f01 = __half22float2(*(__half2*)&v.x);
    float2 f23 = __half22float2(*(__half2*)&v.y);
    wx = pack2(f01.x, f01.y);
    wy = pack2(f23.x, f23.y);
}
__device__ __forceinline__ float sigmoidf_(float z) { return 1.0f / (1.0f + expf(-z)); }
__device__ __forceinline__ float cfc_mix(float a1, float a2, float ac,
                                         float b1, float b2, float bc) {
    float ff1 = tanhf(a1 + b1);
    float ff2 = tanhf(a2 + b2);
    float ti  = sigmoidf_(ac + bc);
    return ff1 + ti * (ff2 - ff1);
}
__device__ __forceinline__ unsigned smem_u32(const void* p) {
    unsigned a;
    asm("{ .reg .u64 t; cvta.to.shared.u64 t, %1; cvt.u32.u64 %0, t; }" : "=r"(a) : "l"(p));
    return a;
}
__device__ __forceinline__ void mbar_init(unsigned addr, unsigned count) {
    asm volatile("mbarrier.init.shared.b64 [%0], %1;" :: "r"(addr), "r"(count) : "memory");
}
__device__ __forceinline__ void mbar_wait(unsigned addr, unsigned parity) {
    unsigned done = 0;
    do {
        asm volatile(
            "{\n\t.reg .pred P;\n\t"
            "mbarrier.try_wait.parity.acquire.cluster.shared::cta.b64 P, [%1], %2, 0x989680;\n\t"
            "selp.b32 %0, 1, 0, P;\n\t}"
            : "=r"(done) : "r"(addr), "r"(parity) : "memory");
    } while (!done);
}
__device__ __forceinline__ void mbar_arrive_local(unsigned addr) {
    asm volatile("mbarrier.arrive.release.cluster.shared::cta.b64 _, [%0];"
                 :: "r"(addr) : "memory");
}
__device__ __forceinline__ void mbar_arrive_peer(unsigned addr, unsigned peer) {
    asm volatile(
        "{\n\t.reg .b32 ra;\n\t"
        "mapa.shared::cluster.u32 ra, %0, %1;\n\t"
        "mbarrier.arrive.release.cluster.shared::cluster.b64 _, [ra];\n\t}"
        :: "r"(addr), "r"(peer) : "memory");
}
__device__ __forceinline__ void cfence() {
    asm volatile("fence.acq_rel.cluster;" ::: "memory");
}
__device__ __forceinline__ void st_peer_u64(unsigned addr, unsigned peer, ull v) {
    asm volatile(
        "{\n\t.reg .b32 ra;\n\t"
        "mapa.shared::cluster.u32 ra, %0, %1;\n\t"
        "st.shared::cluster.u64 [ra], %2;\n\t}"
        :: "r"(addr), "r"(peer), "l"(v) : "memory");
}
__device__ __forceinline__ void st_peer_u32(unsigned addr, unsigned peer, float v) {
    asm volatile(
        "{\n\t.reg .b32 ra;\n\t"
        "mapa.shared::cluster.u32 ra, %0, %1;\n\t"
        "st.shared::cluster.f32 [ra], %2;\n\t}"
        :: "r"(addr), "r"(peer), "f"(v) : "memory");
}
#define BARN(id, n) asm volatile("bar.sync %0, %1;" :: "r"(id), "r"(n) : "memory")

// ---------------------------------------------------------------------------
// Pipelined kernel: 64 clusters x 2 CTAs, 4 rows/cluster, j split across pair;
// warps 0-8 = layer0 (A, LDG fp16 weights w/ deep MLP), 9-13 = layer1
// (B, SMEM-resident fp16 weights), warp 14 = layer2 (C).
// ---------------------------------------------------------------------------
__global__ __launch_bounds__(NTH, 1) __cluster_dims__(2, 1, 1)
void cfc_main_kernel(
    const float* __restrict__ x,
    const float* __restrict__ b1_0, const float* __restrict__ b2_0,
    const float* __restrict__ b1_1, const float* __restrict__ b2_1,
    const float* __restrict__ b1_2, const float* __restrict__ b2_2,
    float* __restrict__ out, int write_h)
{
    extern __shared__ float sm[];
    float* xh0A  = sm + OFF_XH0;
    float* xh1A  = sm + OFF_XH1;
    float* xh2A  = sm + OFF_XH2;
    float* partA = sm + OFF_PARTA;
    float* partB = sm + OFF_PARTB;
    float* sw2   = sm + OFF_SW2;
    __half* sw1h = (__half*)(sm + OFF_SW1);

    const int tid = threadIdx.x;
    unsigned rank;
    asm("mov.u32 %0, %%cluster_ctarank;" : "=r"(rank));
    const unsigned peer = rank ^ 1u;
    const int b0 = (blockIdx.x >> 1) * ROWS;

    const int nj0 = rank ? 73 : 76;
    const int jb0 = rank ? 76 : 0;
    const int nj1 = rank ? 47 : 52;
    const int jb1 = rank ? 52 : 0;

    const unsigned sbase = smem_u32(sm);

    const bool isA = (tid < 288);
    const bool isB = (tid >= 288 && tid < 448);

    // stage A: 57 combos (mat*19+jg) x 5 kc(56)
    const int at = tid;
    const int comboA = at % 57, kcA = at / 57;
    const int matA = comboA / 19, jgA = comboA % 19;
    const bool actA = isA && (at < 285);
    const bool combA = isA && (at < 152);
    const int cjA = at >> 1, crA = (at & 1) * 2;

    // stage B: 39 combos (mat*13+jg) x 4 kc(63)
    const int bt = tid - 288;
    const int comboB = bt % 39, kcB = bt / 39;
    const int matB = comboB / 13, jgB = comboB % 13;
    const bool actB = isB && (bt < 156);
    const bool combB = isB && (bt < 104);
    const int cjB = bt >> 1, crB = (bt & 1) * 2;

    // stage C
    const int ct = tid - 448;
    const int matC = ct >> 3, jC = ct & 7;
    const bool actC = (tid >= 448) && (ct < 24);

    // ---- prologue ----
    for (int i = tid; i < 2 * XB0F; i += NTH) xh0A[i] = 0.f;
    for (int i = tid; i < 2 * XB1F; i += NTH) xh1A[i] = 0.f;
    for (int i = tid; i < 2 * XB2F; i += NTH) xh2A[i] = 0.f;
    for (int i = tid; i < 3 * CAT2 * 8; i += NTH) sw2[i] = ((const float*)g_W2)[i];
    // copy this rank's layer-1 fp16 slice into SMEM (compact stride 156 halfs)
    {
        const unsigned* gw1 = (const unsigned*)g_W1h[rank];
        unsigned* sw1u = (unsigned*)sw1h;
        for (int i = tid; i < K1P * (SS1 / 2); i += NTH) {
            int k = i / (SS1 / 2), c = i - k * (SS1 / 2);
            sw1u[i] = gw1[k * (RS1 / 2) + c];
        }
    }
    if (tid == 0) {
        for (int s = 0; s < 2; ++s) {
            mbar_init(sbase + MB_RDYA(s) * 4, 2);
            mbar_init(sbase + MB_CONB(s) * 4, 2);
            mbar_init(sbase + MB_RDYB(s) * 4, 2);
            mbar_init(sbase + MB_CONC(s) * 4, 2);
        }
    }

    float bA1 = 0.f, bA2 = 0.f, bAc = 0.f;
    if (combA && cjA < nj0) { bA1 = b1_0[jb0 + cjA]; bA2 = b2_0[jb0 + cjA]; bAc = g_bc[jb0 + cjA]; }
    float bB1 = 0.f, bB2 = 0.f, bBc = 0.f;
    if (combB && cjB < nj1) { bB1 = b1_1[jb1 + cjB]; bB2 = b2_1[jb1 + cjB]; bBc = g_bc[NI + jb1 + cjB]; }
    float bC1 = 0.f, bC2 = 0.f, bCc = 0.f;
    if (tid >= 448) { bC1 = b1_2[jC]; bC2 = b2_2[jC]; bCc = g_bc[NI + NCC + jC]; }

    for (int i = tid; i < ROWS * IND; i += NTH) {
        int r = i >> 7, k = i & 127;
        float v = x[((size_t)(b0 + r) * TT + 0) * IND + k];
        *(ull*)&xh0A[k * 8 + r * 2] = pack2(v, v);
    }
    float xr0 = 0.f, xr1 = 0.f;
    const int i0 = tid, i1 = tid + 288;
    if (isA) {
        xr0 = x[((size_t)(b0 + (i0 >> 7)) * TT + 1) * IND + (i0 & 127)];
        if (i1 < ROWS * IND)
            xr1 = x[((size_t)(b0 + (i1 >> 7)) * TT + 1) * IND + (i1 & 127)];
    }

    __syncthreads();
    asm volatile("barrier.cluster.arrive.aligned;" ::: "memory");
    asm volatile("barrier.cluster.wait.aligned;" ::: "memory");

    if (isA) {
        // ============ STAGE A : layer 0 (LDG weights, deep MLP) ============
        const __half* WbA = g_W0h[rank] + (size_t)(kcA * 56) * RS0 + comboA * 4;
        for (int t = 0; t < TT; ++t) {
            const int pr = t & 1, pw = (t + 1) & 1;
            float* xh0r = xh0A + pr * XB0F;
            float* xh0w = xh0A + pw * XB0F;
            float* xh1c = xh1A + pr * XB1F;

            if (t >= 1)
                mbar_wait(sbase + MB_RDYA((t - 1) & 1) * 4, ((t - 1) >> 1) & 1);

            if (actA) {
                const __half* Wp = WbA;
                const float* ab = xh0r + (kcA * 56) * 8;
                ull aA0 = 0, aB0 = 0, aA1 = 0, aB1 = 0;
                ull aA2 = 0, aB2 = 0, aA3 = 0, aB3 = 0;
                #pragma unroll 14
                for (int k = 0; k < 56; ++k) {
                    ull wx, wy;
                    ldw4_h(Wp + (size_t)k * RS0, wx, wy);
                    ulonglong2 d01 = *(const ulonglong2*)(ab + k * 8);
                    ulonglong2 d23 = *(const ulonglong2*)(ab + k * 8 + 4);
                    aA0 = fma2(wx, d01.x, aA0); aB0 = fma2(wy, d01.x, aB0);
                    aA1 = fma2(wx, d01.y, aA1); aB1 = fma2(wy, d01.y, aB1);
                    aA2 = fma2(wx, d23.x, aA2); aB2 = fma2(wy, d23.x, aB2);
                    aA3 = fma2(wx, d23.y, aA3); aB3 = fma2(wy, d23.y, aB3);
                }
                float* P = partA + (size_t)((kcA * 3 + matA) * 4) * 80 + jgA * 4;
                *(ulonglong2*)(P)       = make_ulonglong2(aA0, aB0);
                *(ulonglong2*)(P + 80)  = make_ulonglong2(aA1, aB1);
                *(ulonglong2*)(P + 160) = make_ulonglong2(aA2, aB2);
                *(ulonglong2*)(P + 240) = make_ulonglong2(aA3, aB3);
            }
            BARN(1, 288);

            if (t >= 2)
                mbar_wait(sbase + MB_CONB(t & 1) * 4, ((t - 2) >> 1) & 1);

            if (combA && cjA < nj0) {
                const int r0 = crA, r1 = crA + 1;
                float a1r0 = 0, a1r1 = 0, a2r0 = 0, a2r1 = 0, acr0 = 0, acr1 = 0;
                #pragma unroll
                for (int c = 0; c < 5; ++c) {
                    const float* P = partA + (size_t)(c * 12) * 80;
                    a1r0 += P[(0 * 4 + r0) * 80 + cjA];
                    a1r1 += P[(0 * 4 + r1) * 80 + cjA];
                    a2r0 += P[(1 * 4 + r0) * 80 + cjA];
                    a2r1 += P[(1 * 4 + r1) * 80 + cjA];
                    acr0 += P[(2 * 4 + r0) * 80 + cjA];
                    acr1 += P[(2 * 4 + r1) * 80 + cjA];
                }
                float h0v = cfc_mix(a1r0, a2r0, acr0, bA1, bA2, bAc);
                float h1v = cfc_mix(a1r1, a2r1, acr1, bA1, bA2, bAc);
                ull u0 = pack2(h0v, h0v), u1 = pack2(h1v, h1v);
                const int jg = jb0 + cjA;
                const int oX = (IND + jg) * 8;
                const int oH = jg * 8;
                *(ull*)&xh0w[oX + r0 * 2] = u0;
                *(ull*)&xh0w[oX + r1 * 2] = u1;
                *(ull*)&xh1c[oH + r0 * 2] = u0;
                *(ull*)&xh1c[oH + r1 * 2] = u1;
                st_peer_u64(sbase + (OFF_XH0 + pw * XB0F + oX + r0 * 2) * 4, peer, u0);
                st_peer_u64(sbase + (OFF_XH0 + pw * XB0F + oX + r1 * 2) * 4, peer, u1);
                st_peer_u64(sbase + (OFF_XH1 + pr * XB1F + oH + r0 * 2) * 4, peer, u0);
                st_peer_u64(sbase + (OFF_XH1 + pr * XB1F + oH + r1 * 2) * 4, peer, u1);
            }
            *(ull*)&xh0w[(i0 & 127) * 8 + (i0 >> 7) * 2] = pack2(xr0, xr0);
            if (i1 < ROWS * IND)
                *(ull*)&xh0w[(i1 & 127) * 8 + (i1 >> 7) * 2] = pack2(xr1, xr1);
            {
                int tn = t + 2; if (tn > TT - 1) tn = TT - 1;
                xr0 = x[((size_t)(b0 + (i0 >> 7)) * TT + tn) * IND + (i0 & 127)];
                if (i1 < ROWS * IND)
                    xr1 = x[((size_t)(b0 + (i1 >> 7)) * TT + tn) * IND + (i1 & 127)];
            }
            BARN(1, 288);
            if (tid == 0) {
                cfence();
                mbar_arrive_local(sbase + MB_RDYA(t & 1) * 4);
                mbar_arrive_peer(sbase + MB_RDYA(t & 1) * 4, peer);
            }
        }
    } else if (isB) {
        // ============ STAGE B : layer 1 (SMEM weights) ============
        const __half* WbB = sw1h + (size_t)(kcB * 63) * SS1 + comboB * 4;
        for (int t = 0; t < TT; ++t) {
            const int pr = t & 1, pw = (t + 1) & 1;
            float* xh1r = xh1A + pr * XB1F;
            float* xh1w = xh1A + pw * XB1F;
            float* xh2c = xh2A + pr * XB2F;

            mbar_wait(sbase + MB_RDYA(t & 1) * 4, (t >> 1) & 1);
            if (t >= 1)
                mbar_wait(sbase + MB_RDYB((t - 1) & 1) * 4, ((t - 1) >> 1) & 1);

            if (actB) {
                const __half* Wp = WbB;
                const float* ab = xh1r + (kcB * 63) * 8;
                ull aA0 = 0, aB0 = 0, aA1 = 0, aB1 = 0;
                ull aA2 = 0, aB2 = 0, aA3 = 0, aB3 = 0;
                #pragma unroll 7
                for (int k = 0; k < 63; ++k) {
                    ull wx, wy;
                    ldw4_hs(Wp + (size_t)k * SS1, wx, wy);
                    ulonglong2 d01 = *(const ulonglong2*)(ab + k * 8);
                    ulonglong2 d23 = *(const ulonglong2*)(ab + k * 8 + 4);
                    aA0 = fma2(wx, d01.x, aA0); aB0 = fma2(wy, d01.x, aB0);
                    aA1 = fma2(wx, d01.y, aA1); aB1 = fma2(wy, d01.y, aB1);
                    aA2 = fma2(wx, d23.x, aA2); aB2 = fma2(wy, d23.x, aB2);
                    aA3 = fma2(wx, d23.y, aA3); aB3 = fma2(wy, d23.y, aB3);
                }
                float* P = partB + (size_t)((kcB * 3 + matB) * 4) * 56 + jgB * 4;
                *(ulonglong2*)(P)       = make_ulonglong2(aA0, aB0);
                *(ulonglong2*)(P + 56)  = make_ulonglong2(aA1, aB1);
                *(ulonglong2*)(P + 112) = make_ulonglong2(aA2, aB2);
                *(ulonglong2*)(P + 168) = make_ulonglong2(aA3, aB3);
            }
            BARN(2, 160);
            if (bt == 0) {
                mbar_arrive_local(sbase + MB_CONB(t & 1) * 4);
                mbar_arrive_peer(sbase + MB_CONB(t & 1) * 4, peer);
            }
            if (t >= 2)
                mbar_wait(sbase + MB_CONC(t & 1) * 4, ((t - 2) >> 1) & 1);

            if (combB && cjB < nj1) {
                const int r0 = crB, r1 = crB + 1;
                float a1r0 = 0, a1r1 = 0, a2r0 = 0, a2r1 = 0, acr0 = 0, acr1 = 0;
                #pragma unroll
                for (int c = 0; c < 4; ++c) {
                    const float* P = partB + (size_t)(c * 12) * 56;
                    a1r0 += P[(0 * 4 + r0) * 56 + cjB];
                    a1r1 += P[(0 * 4 + r1) * 56 + cjB];
                    a2r0 += P[(1 * 4 + r0) * 56 + cjB];
                    a2r1 += P[(1 * 4 + r1) * 56 + cjB];
                    acr0 += P[(2 * 4 + r0) * 56 + cjB];
                    acr1 += P[(2 * 4 + r1) * 56 + cjB];
                }
                float h0v = cfc_mix(a1r0, a2r0, acr0, bB1, bB2, bBc);
                float h1v = cfc_mix(a1r1, a2r1, acr1, bB1, bB2, bBc);
                ull u0 = pack2(h0v, h0v), u1 = pack2(h1v, h1v);
                const int jg = jb1 + cjB;
                const int oH = (NI + jg) * 8;
                const int o2 = jg * 4;
                *(ull*)&xh1w[oH + r0 * 2] = u0;
                *(ull*)&xh1w[oH + r1 * 2] = u1;
                xh2c[o2 + r0] = h0v;
                xh2c[o2 + r1] = h1v;
                st_peer_u64(sbase + (OFF_XH1 + pw * XB1F + oH + r0 * 2) * 4, peer, u0);
                st_peer_u64(sbase + (OFF_XH1 + pw * XB1F + oH + r1 * 2) * 4, peer, u1);
                st_peer_u32(sbase + (OFF_XH2 + pr * XB2F + o2 + r0) * 4, peer, h0v);
                st_peer_u32(sbase + (OFF_XH2 + pr * XB2F + o2 + r1) * 4, peer, h1v);
            }
            BARN(2, 160);
            if (bt == 0) {
                cfence();
                mbar_arrive_local(sbase + MB_RDYB(t & 1) * 4);
                mbar_arrive_peer(sbase + MB_RDYB(t & 1) * 4, peer);
            }
        }
    } else {
        // ============ STAGE C : layer 2 ============
        for (int t = 0; t < TT; ++t) {
            const int pr = t & 1, pw = (t + 1) & 1;
            float* xh2r = xh2A + pr * XB2F;
            float* xh2w = xh2A + pw * XB2F;

            mbar_wait(sbase + MB_RDYB(t & 1) * 4, (t >> 1) & 1);

            ull acc01 = 0, acc23 = 0;
            if (actC) {
                const float* W = sw2 + matC * (CAT2 * 8) + jC;
                #pragma unroll 4
                for (int k = 0; k < CAT2; ++k) {
                    float w = W[k * 8];
                    ull ww = pack2(w, w);
                    ulonglong2 u = *(const ulonglong2*)(xh2r + k * 4);
                    acc01 = fma2(ww, u.x, acc01);
                    acc23 = fma2(ww, u.y, acc23);
                }
            }
            __syncwarp();
            if (ct == 0) {
                mbar_arrive_local(sbase + MB_CONC(t & 1) * 4);
                mbar_arrive_peer(sbase + MB_CONC(t & 1) * 4, peer);
            }
            ull m1_01 = __shfl_sync(0xffffffffu, acc01, 8 + jC);
            ull m1_23 = __shfl_sync(0xffffffffu, acc23, 8 + jC);
            ull m2_01 = __shfl_sync(0xffffffffu, acc01, 16 + jC);
            ull m2_23 = __shfl_sync(0xffffffffu, acc23, 16 + jC);
            if (ct < 8) {
                float a1[4], a2[4], ac[4];
                unpack2(acc01, a1[0], a1[1]); unpack2(acc23, a1[2], a1[3]);
                unpack2(m1_01, a2[0], a2[1]); unpack2(m1_23, a2[2], a2[3]);
                unpack2(m2_01, ac[0], ac[1]); unpack2(m2_23, ac[2], ac[3]);
                #pragma unroll
                for (int r = 0; r < 4; ++r) {
                    float h = cfc_mix(a1[r], a2[r], ac[r], bC1, bC2, bCc);
                    xh2w[(NCC + jC) * 4 + r] = h;
                    if (rank == 0)
                        out[((size_t)(b0 + r) * TT + t) * NM + jC] = tanhf(h);
                }
            }
            __syncwarp();
        }
    }

    __syncthreads();
    asm volatile("barrier.cluster.arrive.aligned;" ::: "memory");
    asm volatile("barrier.cluster.wait.aligned;" ::: "memory");
    cfence();

    if (write_h && rank == 0) {
        size_t base = (size_t)BB * TT * NM;
        for (int jt = tid; jt < 256; jt += NTH) {
            #pragma unroll
            for (int r = 0; r < 4; ++r) {
                float v;
                if (jt < NI)            v = xh0A[(IND + jt) * 8 + r * 2];
                else if (jt < NI + NCC) v = xh1A[(NI + (jt - NI)) * 8 + r * 2];
                else                    v = xh2A[(NCC + (jt - NI - NCC)) * 4 + r];
                out[base + (size_t)(b0 + r) * 256 + jt] = v;
            }
        }
    }
    asm volatile("barrier.cluster.arrive.aligned;" ::: "memory");
    asm volatile("barrier.cluster.wait.aligned;" ::: "memory");
}

// ---------------------------------------------------------------------------
extern "C" void kernel_launch(void* const* d_in, const int* in_sizes, int n_in,
                              void* d_out, int out_size)
{
    const float *x, *dt;
    const float *w1[3], *b1[3], *w2[3], *b2[3], *wa[3], *ba[3], *wb[3], *bb[3];
    const int   *m[3];

    if (in_sizes[0] == BB * TT * IND) {
        x  = (const float*)d_in[0];
        dt = (const float*)d_in[1];
        for (int l = 0; l < 3; l++) {
            int base = 2 + 9 * l;
            w1[l] = (const float*)d_in[base + 0];
            b1[l] = (const float*)d_in[base + 1];
            w2[l] = (const float*)d_in[base + 2];
            b2[l] = (const float*)d_in[base + 3];
            wa[l] = (const float*)d_in[base + 4];
            ba[l] = (const float*)d_in[base + 5];
            wb[l] = (const float*)d_in[base + 6];
            bb[l] = (const float*)d_in[base + 7];
            m[l]  = (const int*)  d_in[base + 8];
        }
    } else {
        for (int l = 0; l < 3; l++) {
            int base = 9 * l;
            w1[l] = (const float*)d_in[base + 0];
            w2[l] = (const float*)d_in[base + 1];
            wa[l] = (const float*)d_in[base + 2];
            wb[l] = (const float*)d_in[base + 3];
            b1[l] = (const float*)d_in[base + 4];
            b2[l] = (const float*)d_in[base + 5];
            ba[l] = (const float*)d_in[base + 6];
            bb[l] = (const float*)d_in[base + 7];
            m[l]  = (const int*)  d_in[base + 8];
        }
        x  = (const float*)d_in[27];
        dt = (const float*)d_in[28];
    }

    cfc_precompute_kernel<<<148, 256>>>(
        w1[0], w2[0], wa[0], wb[0], ba[0], bb[0], m[0],
        w1[1], w2[1], wa[1], wb[1], ba[1], bb[1], m[1],
        w1[2], w2[2], wa[2], wb[2], ba[2], bb[2], m[2],
        dt);

    cudaFuncSetAttribute(cfc_main_kernel,
                         cudaFuncAttributeMaxDynamicSharedMemorySize, SMEM_BYTES);

    int write_h = (out_size >= BB * TT * NM + BB * 256) ? 1 : 0;
    cfc_main_kernel<<<(BB / ROWS) * 2, NTH, SMEM_BYTES>>>(
        x, b1[0], b2[0], b1[1], b2[1], b1[2], b2[2],
        (float*)d_out, write_h);
}